// round 2
// baseline (speedup 1.0000x reference)
#include <cuda_runtime.h>
#include <stdint.h>

// Problem constants (shapes fixed by the dataset; N/E still derived from in_sizes)
#define NODES_MAX 50000
#define HID 128
#define ZD 64
#define NPB 16          // nodes per block in K0
#define TILE_E 64       // edges per tile in K2
#define SH_STRIDE 132   // padded h-row stride (floats) in K2 smem
#define K1_BLOCKS 1184  // 148 SMs * 8
#define K2_BLOCKS 296   // 148 SMs * 2

// ---------------- static device scratch (no allocs allowed) ----------------
__device__ float  g_A[NODES_MAX * HID];   // z @ W1[0:64]
__device__ float  g_B[NODES_MAX * HID];   // z @ W1[64:128]
__device__ float  g_d[HID];               // c @ W1[128:132] + b1
__device__ double g_sum[HID];
__device__ double g_sumsq[HID];
__device__ float  g_W2p[HID * HID];       // BN-folded W2, pair-interleaved layout
__device__ float  g_b2p[HID];             // BN-folded b2
__device__ int    g_is64;                 // edge_index dtype flag (1 = int64, 0 = int32)

// ---------------- edge-index load helper (dtype-agnostic, clamped) ----------------
__device__ __forceinline__ int ld_idx(const void* ei, long long pos, int is64, int N) {
    int v = is64 ? (int)((const long long*)ei)[pos] : ((const int*)ei)[pos];
    // clamp: converts any residual addressing bug into a rel_err signal, not a crash
    v = v < 0 ? 0 : (v >= N ? N - 1 : v);
    return v;
}

// ---------------- f32x2 packed-FMA helpers (FFMA2 on sm_103a) ----------------
__device__ __forceinline__ unsigned long long pack2(float lo, float hi) {
    unsigned long long r;
    asm("mov.b64 %0, {%1, %2};" : "=l"(r) : "f"(lo), "f"(hi));
    return r;
}
__device__ __forceinline__ void unpack2(unsigned long long v, float& lo, float& hi) {
    asm("mov.b64 {%0, %1}, %2;" : "=f"(lo), "=f"(hi) : "l"(v));
}
__device__ __forceinline__ unsigned long long ffma2(unsigned long long a,
                                                    unsigned long long b,
                                                    unsigned long long c) {
    unsigned long long d;
    asm("fma.rn.f32x2 %0, %1, %2, %3;" : "=l"(d) : "l"(a), "l"(b), "l"(c));
    return d;
}

// ---------------- K_detect: is edge_index int64 or int32? ----------------
// Interpret first 128 entries as int64; if ALL high words are 0 -> int64.
// (int32 data: each "high word" is a random index in [0,50000); P[all 128 == 0] ~ 0.)
__global__ void k_detect(const unsigned int* __restrict__ w) {
    __shared__ int nz;
    int t = threadIdx.x;
    if (t == 0) nz = 0;
    __syncthreads();
    if (w[2 * t + 1] != 0u) atomicAdd(&nz, 1);
    __syncthreads();
    if (t == 0) g_is64 = (nz == 0) ? 1 : 0;
}

// ---------------- K0: per-node partial products A = z@W1s, B = z@W1d ----------------
__global__ void k0_nodes(const float* __restrict__ z, const float* __restrict__ W1, int N) {
    __shared__ float zs[NPB * ZD];
    int tid  = threadIdx.x;             // output feature j (0..127)
    int base = blockIdx.x * NPB;
    int nn   = N - base; if (nn > NPB) nn = NPB;

    for (int i = tid; i < nn * ZD; i += 128) zs[i] = z[base * ZD + i];
    __syncthreads();

    float a[NPB], b[NPB];
#pragma unroll
    for (int n = 0; n < NPB; n++) { a[n] = 0.f; b[n] = 0.f; }

#pragma unroll 8
    for (int k = 0; k < ZD; k++) {
        float ws = W1[k * HID + tid];          // src-part column (L1-resident)
        float wd = W1[(ZD + k) * HID + tid];   // dst-part column
#pragma unroll
        for (int n = 0; n < NPB; n++) {
            float zk = zs[n * ZD + k];         // smem broadcast
            a[n] = fmaf(zk, ws, a[n]);
            b[n] = fmaf(zk, wd, b[n]);
        }
    }
    for (int n = 0; n < nn; n++) {
        g_A[(base + n) * HID + tid] = a[n];
        g_B[(base + n) * HID + tid] = b[n];
    }
}

// ---------------- K0b: d = c@W1c + b1 ; zero BN accumulators ----------------
__global__ void k0b_init(const float* __restrict__ c, const float* __restrict__ W1,
                         const float* __restrict__ b1) {
    int j = threadIdx.x;
    float v = b1[j];
#pragma unroll
    for (int k = 0; k < 4; k++) v = fmaf(c[k], W1[(2 * ZD + k) * HID + j], v);
    g_d[j]     = v;
    g_sum[j]   = 0.0;
    g_sumsq[j] = 0.0;
}

// ---------------- K1: BN statistics pass over edges ----------------
__global__ void k1_stats(const void* __restrict__ ei, int E, int N) {
    int j = threadIdx.x;  // feature
    int is64 = g_is64;
    float dreg = g_d[j];

    int per = (E + gridDim.x - 1) / (int)gridDim.x;
    int e0 = blockIdx.x * per;
    int e1 = e0 + per; if (e1 > E) e1 = E;

    float s1 = 0.f, s2 = 0.f;
    int e = e0;
    for (; e + 4 <= e1; e += 4) {
        int sa = ld_idx(ei, e,     is64, N), sb = ld_idx(ei, e + 1, is64, N);
        int sc = ld_idx(ei, e + 2, is64, N), sd = ld_idx(ei, e + 3, is64, N);
        int ta = ld_idx(ei, (long long)E + e,     is64, N), tb = ld_idx(ei, (long long)E + e + 1, is64, N);
        int tc = ld_idx(ei, (long long)E + e + 2, is64, N), td = ld_idx(ei, (long long)E + e + 3, is64, N);
        float a0 = g_A[sa*HID + j], a1 = g_A[sb*HID + j], a2 = g_A[sc*HID + j], a3 = g_A[sd*HID + j];
        float v0 = g_B[ta*HID + j], v1 = g_B[tb*HID + j], v2 = g_B[tc*HID + j], v3 = g_B[td*HID + j];
        float h0 = fmaxf(a0 + v0 + dreg, 0.f);
        float h1 = fmaxf(a1 + v1 + dreg, 0.f);
        float h2 = fmaxf(a2 + v2 + dreg, 0.f);
        float h3 = fmaxf(a3 + v3 + dreg, 0.f);
        s1 += h0 + h1 + h2 + h3;
        s2 = fmaf(h0, h0, s2); s2 = fmaf(h1, h1, s2);
        s2 = fmaf(h2, h2, s2); s2 = fmaf(h3, h3, s2);
    }
    for (; e < e1; e++) {
        int s = ld_idx(ei, e, is64, N);
        int t = ld_idx(ei, (long long)E + e, is64, N);
        float h = fmaxf(g_A[s*HID + j] + g_B[t*HID + j] + dreg, 0.f);
        s1 += h; s2 = fmaf(h, h, s2);
    }
    atomicAdd(&g_sum[j],   (double)s1);
    atomicAdd(&g_sumsq[j], (double)s2);
}

// ---------------- K1.5: fold BN into W2/b2 (pair-interleaved layout for K2) ----------------
// Layout: slot(k, f) = k*128 + p*32 + fg*2 + half, where f = fg + 16p + 64*half.
__global__ void k15_fold(const float* __restrict__ gamma, const float* __restrict__ beta,
                         const float* __restrict__ W2, const float* __restrict__ b2,
                         double invE) {
    __shared__ float gsc[HID], gsh[HID];
    int i = threadIdx.x;  // output feature of layer 2

    double m = g_sum[i] * invE;
    double v = g_sumsq[i] * invE - m * m;
    float x = (float)v + 1e-5f;
    float s = rsqrtf(x);
    s = s * (1.5f - 0.5f * x * s * s);  // Newton refine
    float g = s * gamma[i];
    gsc[i] = g;
    gsh[i] = beta[i] - (float)m * g;
    __syncthreads();

    int half = i >> 6, fr = i & 63, p = fr >> 4, fg = fr & 15;
    int slot = p * 32 + fg * 2 + half;
    float bb = b2[i];
    for (int j = 0; j < HID; j++) {
        float w = W2[j * HID + i];
        g_W2p[j * HID + slot] = gsc[j] * w;
        bb = fmaf(gsh[j], w, bb);
    }
    g_b2p[i] = bb;
}

// ---------------- K2: fused gather + GEMM2 + ReLU + W3 dot ----------------
// blockDim=128: fg = tid&15 (16 feature-groups of 8 strided feats), eg = tid>>4 (8 edge-groups of 8).
// Per-thread register tile: 8 edges x 8 features = 32 f32x2 accumulators.
__global__ void __launch_bounds__(128, 2)
k2_main(const void* __restrict__ ei, const float* __restrict__ W3,
        const float* __restrict__ b3, float* __restrict__ out, int E, int N, int ntiles) {
    extern __shared__ float smem[];
    float* sW = smem;                 // HID*HID = 16384 floats (pair-interleaved W2')
    float* sh = smem + HID * HID;     // TILE_E rows of SH_STRIDE floats (relu(h))
    __shared__ int sidx[2 * TILE_E];

    int tid = threadIdx.x;
    int fg  = tid & 15;
    int eg  = tid >> 4;
    int is64 = g_is64;

    // stage W2' into smem (once per block)
    for (int i = tid; i < HID * HID; i += 128) sW[i] = g_W2p[i];

    // per-thread constants
    float dreg = g_d[tid];
    float b2r[8], w3r[8];
#pragma unroll
    for (int p = 0; p < 4; p++) {
#pragma unroll
        for (int h = 0; h < 2; h++) {
            int f = fg + 16 * p + 64 * h;
            b2r[p * 2 + h] = g_b2p[f];
            w3r[p * 2 + h] = W3[f];
        }
    }
    float bias3 = b3[0];

    for (int tile = blockIdx.x; tile < ntiles; tile += gridDim.x) {
        int base = tile * TILE_E;

        if (tid < TILE_E) {
            int e = base + tid;
            sidx[tid] = (e < E) ? ld_idx(ei, e, is64, N) : 0;
        } else {
            int e = base + tid - TILE_E;
            sidx[tid] = (e < E) ? ld_idx(ei, (long long)E + e, is64, N) : 0;
        }
        __syncthreads();  // sidx ready; also fences prev-tile smem reads & sW on first iter

        // gather phase: h[e][k=tid] = relu(A[src][k] + B[dst][k] + d[k])
#pragma unroll 4
        for (int e = 0; e < TILE_E; e++) {
            int s = sidx[e], t = sidx[TILE_E + e];
            float h = g_A[s * HID + tid] + g_B[t * HID + tid] + dreg;
            sh[e * SH_STRIDE + tid] = fmaxf(h, 0.f);
        }
        __syncthreads();

        // GEMM phase
        unsigned long long acc[8][4];
#pragma unroll
        for (int e = 0; e < 8; e++)
#pragma unroll
            for (int p = 0; p < 4; p++) acc[e][p] = 0ull;

        const float* shb = sh + (eg * 8) * SH_STRIDE;
        for (int k4 = 0; k4 < HID / 4; k4++) {
            float4 hq[8];
#pragma unroll
            for (int e = 0; e < 8; e++)
                hq[e] = *reinterpret_cast<const float4*>(shb + e * SH_STRIDE + k4 * 4);
#pragma unroll
            for (int kk = 0; kk < 4; kk++) {
                int k = k4 * 4 + kk;
                const float* wrow = sW + k * HID + fg * 2;
                unsigned long long w0 = *reinterpret_cast<const unsigned long long*>(wrow);
                unsigned long long w1 = *reinterpret_cast<const unsigned long long*>(wrow + 32);
                unsigned long long w2 = *reinterpret_cast<const unsigned long long*>(wrow + 64);
                unsigned long long w3 = *reinterpret_cast<const unsigned long long*>(wrow + 96);
#pragma unroll
                for (int e = 0; e < 8; e++) {
                    float hv = (kk == 0) ? hq[e].x : (kk == 1) ? hq[e].y
                             : (kk == 2) ? hq[e].z : hq[e].w;
                    unsigned long long hh = pack2(hv, hv);
                    acc[e][0] = ffma2(hh, w0, acc[e][0]);
                    acc[e][1] = ffma2(hh, w1, acc[e][1]);
                    acc[e][2] = ffma2(hh, w2, acc[e][2]);
                    acc[e][3] = ffma2(hh, w3, acc[e][3]);
                }
            }
        }

        // epilogue: relu + W3 dot, reduce across the 16 feature-groups (half-warp shfl)
#pragma unroll
        for (int e = 0; e < 8; e++) {
            float partial = 0.f;
#pragma unroll
            for (int p = 0; p < 4; p++) {
                float lo, hi;
                unpack2(acc[e][p], lo, hi);
                partial = fmaf(fmaxf(lo + b2r[p * 2 + 0], 0.f), w3r[p * 2 + 0], partial);
                partial = fmaf(fmaxf(hi + b2r[p * 2 + 1], 0.f), w3r[p * 2 + 1], partial);
            }
            partial += __shfl_down_sync(0xffffffffu, partial, 8, 16);
            partial += __shfl_down_sync(0xffffffffu, partial, 4, 16);
            partial += __shfl_down_sync(0xffffffffu, partial, 2, 16);
            partial += __shfl_down_sync(0xffffffffu, partial, 1, 16);
            if (fg == 0) {
                int ge = base + eg * 8 + e;
                if (ge < E) out[ge] = partial + bias3;
            }
        }
        __syncthreads();  // all sh reads done before next tile overwrites
    }
}

// ---------------- launch ----------------
extern "C" void kernel_launch(void* const* d_in, const int* in_sizes, int n_in,
                              void* d_out, int out_size) {
    const float* z     = (const float*)d_in[0];
    const void*  ei    = d_in[1];
    const float* c     = (const float*)d_in[2];
    const float* W1    = (const float*)d_in[3];
    const float* b1    = (const float*)d_in[4];
    const float* gamma = (const float*)d_in[5];
    const float* beta  = (const float*)d_in[6];
    const float* W2    = (const float*)d_in[7];
    const float* b2    = (const float*)d_in[8];
    const float* W3    = (const float*)d_in[9];
    const float* b3    = (const float*)d_in[10];
    float* out = (float*)d_out;

    int N = in_sizes[0] / ZD;
    int E = in_sizes[1] / 2;

    int smem_bytes = (HID * HID + TILE_E * SH_STRIDE) * (int)sizeof(float);
    cudaFuncSetAttribute(k2_main, cudaFuncAttributeMaxDynamicSharedMemorySize, smem_bytes);

    k_detect<<<1, 128>>>((const unsigned int*)ei);
    k0_nodes<<<(N + NPB - 1) / NPB, 128>>>(z, W1, N);
    k0b_init<<<1, 128>>>(c, W1, b1);
    k1_stats<<<K1_BLOCKS, 128>>>(ei, E, N);
    k15_fold<<<1, 128>>>(gamma, beta, W2, b2, 1.0 / (double)E);
    int ntiles = (E + TILE_E - 1) / TILE_E;
    k2_main<<<K2_BLOCKS, 128, smem_bytes>>>(ei, W3, b3, out, E, N, ntiles);
}

// round 3
// speedup vs baseline: 1.1598x; 1.1598x over previous
#include <cuda_runtime.h>
#include <stdint.h>

// Problem constants (shapes fixed by the dataset; N/E still derived from in_sizes)
#define NODES_MAX 50000
#define HID 128
#define ZD 64
#define NPB 16          // nodes per block in K0
#define TE2 64          // edges per tile in K2
#define K1_BLOCKS 1184  // 148 SMs * 8
#define K2_GRID 148     // persistent, 1 block/SM (128KB smem)

typedef unsigned long long u64;

// ---------------- static device scratch (no allocs allowed) ----------------
__device__ float  g_A[NODES_MAX * HID];   // z @ W1[0:64]
__device__ float  g_B[NODES_MAX * HID];   // z @ W1[64:128]
__device__ float  g_d[HID];               // c @ W1[128:132] + b1
__device__ double g_sum[HID];
__device__ double g_sumsq[HID];
__device__ float  g_W2p[HID * HID];       // BN-folded W2, pair-interleaved layout
__device__ float  g_b2p[HID];             // BN-folded b2
__device__ int    g_is64;                 // edge_index dtype flag (1 = int64, 0 = int32)

// ---------------- f32x2 packed-FMA helpers (FFMA2 on sm_103a) ----------------
__device__ __forceinline__ u64 pack2(float lo, float hi) {
    u64 r;
    asm("mov.b64 %0, {%1, %2};" : "=l"(r) : "f"(lo), "f"(hi));
    return r;
}
__device__ __forceinline__ void unpack2(u64 v, float& lo, float& hi) {
    asm("mov.b64 {%0, %1}, %2;" : "=f"(lo), "=f"(hi) : "l"(v));
}
__device__ __forceinline__ u64 ffma2(u64 a, u64 b, u64 c) {
    u64 d;
    asm("fma.rn.f32x2 %0, %1, %2, %3;" : "=l"(d) : "l"(a), "l"(b), "l"(c));
    return d;
}

// ---------------- K_detect: is edge_index int64 or int32? ----------------
__global__ void k_detect(const unsigned int* __restrict__ w) {
    __shared__ int nz;
    int t = threadIdx.x;
    if (t == 0) nz = 0;
    __syncthreads();
    if (w[2 * t + 1] != 0u) atomicAdd(&nz, 1);
    __syncthreads();
    if (t == 0) g_is64 = (nz == 0) ? 1 : 0;
}

// ---------------- K0: per-node partial products A = z@W1s, B = z@W1d ----------------
__global__ void k0_nodes(const float* __restrict__ z, const float* __restrict__ W1, int N) {
    __shared__ float zs[NPB * ZD];
    int tid  = threadIdx.x;
    int base = blockIdx.x * NPB;
    int nn   = N - base; if (nn > NPB) nn = NPB;

    for (int i = tid; i < nn * ZD; i += 128) zs[i] = z[base * ZD + i];
    __syncthreads();

    float a[NPB], b[NPB];
#pragma unroll
    for (int n = 0; n < NPB; n++) { a[n] = 0.f; b[n] = 0.f; }

#pragma unroll 8
    for (int k = 0; k < ZD; k++) {
        float ws = W1[k * HID + tid];
        float wd = W1[(ZD + k) * HID + tid];
#pragma unroll
        for (int n = 0; n < NPB; n++) {
            float zk = zs[n * ZD + k];
            a[n] = fmaf(zk, ws, a[n]);
            b[n] = fmaf(zk, wd, b[n]);
        }
    }
    for (int n = 0; n < nn; n++) {
        g_A[(base + n) * HID + tid] = a[n];
        g_B[(base + n) * HID + tid] = b[n];
    }
}

// ---------------- K0b: d = c@W1c + b1 ; zero BN accumulators ----------------
__global__ void k0b_init(const float* __restrict__ c, const float* __restrict__ W1,
                         const float* __restrict__ b1) {
    int j = threadIdx.x;
    float v = b1[j];
#pragma unroll
    for (int k = 0; k < 4; k++) v = fmaf(c[k], W1[(2 * ZD + k) * HID + j], v);
    g_d[j]     = v;
    g_sum[j]   = 0.0;
    g_sumsq[j] = 0.0;
}

// ---------------- K1: BN statistics pass over edges (dtype-specialized) ----------------
template<bool IS64>
__device__ __forceinline__ int ldi(const void* ei, long long pos) {
    return IS64 ? (int)((const long long*)ei)[pos] : ((const int*)ei)[pos];
}

template<bool IS64>
__device__ __forceinline__ void k1_body(const void* __restrict__ ei, int E) {
    int j = threadIdx.x;
    float dreg = g_d[j];

    int per = (E + gridDim.x - 1) / (int)gridDim.x;
    int e0 = blockIdx.x * per;
    int e1 = e0 + per; if (e1 > E) e1 = E;

    float s1 = 0.f, s2 = 0.f;
    int e = e0;
    for (; e + 8 <= e1; e += 8) {
        int s[8], t[8];
#pragma unroll
        for (int i = 0; i < 8; i++) s[i] = ldi<IS64>(ei, e + i);
#pragma unroll
        for (int i = 0; i < 8; i++) t[i] = ldi<IS64>(ei, (long long)E + e + i);
        float av[8], bv[8];
#pragma unroll
        for (int i = 0; i < 8; i++) { av[i] = g_A[s[i] * HID + j]; bv[i] = g_B[t[i] * HID + j]; }
#pragma unroll
        for (int i = 0; i < 8; i++) {
            float h = fmaxf(av[i] + bv[i] + dreg, 0.f);
            s1 += h; s2 = fmaf(h, h, s2);
        }
    }
    for (; e < e1; e++) {
        int s = ldi<IS64>(ei, e);
        int t = ldi<IS64>(ei, (long long)E + e);
        float h = fmaxf(g_A[s * HID + j] + g_B[t * HID + j] + dreg, 0.f);
        s1 += h; s2 = fmaf(h, h, s2);
    }
    atomicAdd(&g_sum[j],   (double)s1);
    atomicAdd(&g_sumsq[j], (double)s2);
}

__global__ void k1_stats(const void* __restrict__ ei, int E) {
    if (g_is64) k1_body<true>(ei, E);
    else        k1_body<false>(ei, E);
}

// ---------------- K1.5: fold BN into W2/b2 (pair-interleaved layout for K2) ----------------
// Layout: slot(k, f) = k*128 + p*32 + fg*2 + half, where f = fg + 16p + 64*half.
__global__ void k15_fold(const float* __restrict__ gamma, const float* __restrict__ beta,
                         const float* __restrict__ W2, const float* __restrict__ b2,
                         double invE) {
    __shared__ float gsc[HID], gsh[HID];
    int i = threadIdx.x;

    double m = g_sum[i] * invE;
    double v = g_sumsq[i] * invE - m * m;
    float x = (float)v + 1e-5f;
    float s = rsqrtf(x);
    s = s * (1.5f - 0.5f * x * s * s);  // Newton refine
    float g = s * gamma[i];
    gsc[i] = g;
    gsh[i] = beta[i] - (float)m * g;
    __syncthreads();

    int half = i >> 6, fr = i & 63, p = fr >> 4, fg = fr & 15;
    int slot = p * 32 + fg * 2 + half;
    float bb = b2[i];
    for (int j = 0; j < HID; j++) {
        float w = W2[j * HID + i];
        g_W2p[j * HID + slot] = gsc[j] * w;
        bb = fmaf(gsh[j], w, bb);
    }
    g_b2p[i] = bb;
}

// ---------------- K2: fused gather + GEMM2 + ReLU + W3 dot ----------------
// 256 threads. Compute map: fg=tid&15 (8 strided features), eg=tid>>4 (4 edges).
// Gather map: ge=tid&63 (edge), kq=tid>>6 (32-k quarter).
// sh2 holds h pre-duplicated as (h,h) u64 -> FFMA2 needs NO pack MOVs.
// Next tile's A/B rows are register-staged (LDG in flight during the FMA loop).
__global__ void __launch_bounds__(256, 1)
k2_main(const void* __restrict__ ei, const float* __restrict__ W3,
        const float* __restrict__ b3, float* __restrict__ out, int E, int ntiles) {
    extern __shared__ float smem[];
    float* sW = smem;                        // 16384 floats (pair-interleaved W2')
    u64*   sh2 = (u64*)(smem + HID * HID);   // [128][TE2] duplicated h pairs (64KB)
    __shared__ float sd[HID];

    int tid = threadIdx.x;
    int fg = tid & 15, eg = tid >> 4;
    int ge = tid & 63, kq = tid >> 6;
    bool is64 = (g_is64 != 0);

    for (int i = tid; i < HID * HID; i += 256) sW[i] = g_W2p[i];
    if (tid < HID) sd[tid] = g_d[tid];

    float b2r[8], w3r[8];
#pragma unroll
    for (int p = 0; p < 4; p++)
#pragma unroll
        for (int h = 0; h < 2; h++) {
            int f = fg + 16 * p + 64 * h;
            b2r[p * 2 + h] = g_b2p[f];
            w3r[p * 2 + h] = W3[f];
        }
    float bias3 = b3[0];
    __syncthreads();

    const long long* p64 = (const long long*)ei;
    const int*       p32 = (const int*)ei;

    float4 areg[8], breg[8];
    int tile = blockIdx.x;

    // prefetch tile0 into registers
    {
        int e = tile * TE2 + ge;
        int s = 0, t = 0;
        if (e < E) {
            s = is64 ? (int)p64[e] : p32[e];
            t = is64 ? (int)p64[(long long)E + e] : p32[(long long)E + e];
        }
        const float4* ap = (const float4*)(g_A + (size_t)s * HID + kq * 32);
        const float4* bp = (const float4*)(g_B + (size_t)t * HID + kq * 32);
#pragma unroll
        for (int i = 0; i < 8; i++) { areg[i] = ap[i]; breg[i] = bp[i]; }
    }

    while (tile < ntiles) {
        // ---- transform: h = relu(a+b+d), store duplicated (h,h) into sh2[k][e] ----
#pragma unroll
        for (int i = 0; i < 8; i++) {
            int kb = kq * 32 + i * 4;
            float h0 = fmaxf(areg[i].x + breg[i].x + sd[kb + 0], 0.f);
            float h1 = fmaxf(areg[i].y + breg[i].y + sd[kb + 1], 0.f);
            float h2 = fmaxf(areg[i].z + breg[i].z + sd[kb + 2], 0.f);
            float h3 = fmaxf(areg[i].w + breg[i].w + sd[kb + 3], 0.f);
            sh2[(kb + 0) * TE2 + ge] = pack2(h0, h0);
            sh2[(kb + 1) * TE2 + ge] = pack2(h1, h1);
            sh2[(kb + 2) * TE2 + ge] = pack2(h2, h2);
            sh2[(kb + 3) * TE2 + ge] = pack2(h3, h3);
        }
        __syncthreads();

        // ---- prefetch next tile (LDGs fly during the FMA loop below) ----
        int next = tile + gridDim.x;
        if (next < ntiles) {
            int e = next * TE2 + ge;
            int s = 0, t = 0;
            if (e < E) {
                s = is64 ? (int)p64[e] : p32[e];
                t = is64 ? (int)p64[(long long)E + e] : p32[(long long)E + e];
            }
            const float4* ap = (const float4*)(g_A + (size_t)s * HID + kq * 32);
            const float4* bp = (const float4*)(g_B + (size_t)t * HID + kq * 32);
#pragma unroll
            for (int i = 0; i < 8; i++) { areg[i] = ap[i]; breg[i] = bp[i]; }
        }

        // ---- GEMM phase: acc[4 edges][4 feature-pairs] ----
        u64 acc[4][4];
#pragma unroll
        for (int a = 0; a < 4; a++)
#pragma unroll
            for (int p = 0; p < 4; p++) acc[a][p] = 0ull;

        const u64*   hrow = sh2 + eg * 4;
        const float* wcol = sW + fg * 2;
#pragma unroll 4
        for (int k = 0; k < HID; k++) {
            ulonglong2 h01 = *(const ulonglong2*)(hrow + k * TE2);
            ulonglong2 h23 = *(const ulonglong2*)(hrow + k * TE2 + 2);
            const float* wr = wcol + k * HID;
            u64 w0 = *(const u64*)(wr);
            u64 w1 = *(const u64*)(wr + 32);
            u64 w2 = *(const u64*)(wr + 64);
            u64 w3 = *(const u64*)(wr + 96);
            acc[0][0] = ffma2(h01.x, w0, acc[0][0]);
            acc[0][1] = ffma2(h01.x, w1, acc[0][1]);
            acc[0][2] = ffma2(h01.x, w2, acc[0][2]);
            acc[0][3] = ffma2(h01.x, w3, acc[0][3]);
            acc[1][0] = ffma2(h01.y, w0, acc[1][0]);
            acc[1][1] = ffma2(h01.y, w1, acc[1][1]);
            acc[1][2] = ffma2(h01.y, w2, acc[1][2]);
            acc[1][3] = ffma2(h01.y, w3, acc[1][3]);
            acc[2][0] = ffma2(h23.x, w0, acc[2][0]);
            acc[2][1] = ffma2(h23.x, w1, acc[2][1]);
            acc[2][2] = ffma2(h23.x, w2, acc[2][2]);
            acc[2][3] = ffma2(h23.x, w3, acc[2][3]);
            acc[3][0] = ffma2(h23.y, w0, acc[3][0]);
            acc[3][1] = ffma2(h23.y, w1, acc[3][1]);
            acc[3][2] = ffma2(h23.y, w2, acc[3][2]);
            acc[3][3] = ffma2(h23.y, w3, acc[3][3]);
        }

        // ---- epilogue: relu + W3 dot, reduce across 16 feature-groups ----
        int base = tile * TE2;
#pragma unroll
        for (int a = 0; a < 4; a++) {
            float partial = 0.f;
#pragma unroll
            for (int p = 0; p < 4; p++) {
                float lo, hi;
                unpack2(acc[a][p], lo, hi);
                partial = fmaf(fmaxf(lo + b2r[p * 2 + 0], 0.f), w3r[p * 2 + 0], partial);
                partial = fmaf(fmaxf(hi + b2r[p * 2 + 1], 0.f), w3r[p * 2 + 1], partial);
            }
            partial += __shfl_down_sync(0xffffffffu, partial, 8, 16);
            partial += __shfl_down_sync(0xffffffffu, partial, 4, 16);
            partial += __shfl_down_sync(0xffffffffu, partial, 2, 16);
            partial += __shfl_down_sync(0xffffffffu, partial, 1, 16);
            if (fg == 0) {
                int geo = base + eg * 4 + a;
                if (geo < E) out[geo] = partial + bias3;
            }
        }
        __syncthreads();  // all sh2 reads done before next transform overwrites
        tile = next;
    }
}

// ---------------- launch ----------------
extern "C" void kernel_launch(void* const* d_in, const int* in_sizes, int n_in,
                              void* d_out, int out_size) {
    const float* z     = (const float*)d_in[0];
    const void*  ei    = d_in[1];
    const float* c     = (const float*)d_in[2];
    const float* W1    = (const float*)d_in[3];
    const float* b1    = (const float*)d_in[4];
    const float* gamma = (const float*)d_in[5];
    const float* beta  = (const float*)d_in[6];
    const float* W2    = (const float*)d_in[7];
    const float* b2    = (const float*)d_in[8];
    const float* W3    = (const float*)d_in[9];
    const float* b3    = (const float*)d_in[10];
    float* out = (float*)d_out;

    int N = in_sizes[0] / ZD;
    int E = in_sizes[1] / 2;

    int smem_bytes = HID * HID * (int)sizeof(float) + HID * TE2 * (int)sizeof(u64);  // 128KB
    cudaFuncSetAttribute(k2_main, cudaFuncAttributeMaxDynamicSharedMemorySize, smem_bytes);

    k_detect<<<1, 128>>>((const unsigned int*)ei);
    k0_nodes<<<(N + NPB - 1) / NPB, 128>>>(z, W1, N);
    k0b_init<<<1, 128>>>(c, W1, b1);
    k1_stats<<<K1_BLOCKS, 128>>>(ei, E);
    k15_fold<<<1, 128>>>(gamma, beta, W2, b2, 1.0 / (double)E);
    int ntiles = (E + TE2 - 1) / TE2;
    k2_main<<<K2_GRID, 256, smem_bytes>>>(ei, W3, b3, out, E, ntiles);
}

// round 5
// speedup vs baseline: 2.0274x; 1.7481x over previous
#include <cuda_runtime.h>
#include <cuda_bf16.h>
#include <stdint.h>

#define NODES_MAX 50000
#define HID 128
#define ZD 64
#define NPB 16          // nodes per block in K0
#define TM 128          // edges per tile in K2
#define K1_BLOCKS 1184  // 148 SMs * 8
#define K2_GRID 148

typedef unsigned long long u64;
typedef unsigned int u32;

// ---------------- static device scratch ----------------
__device__ float  g_A[NODES_MAX * HID];     // z @ W1[0:64]
__device__ float  g_B[NODES_MAX * HID];     // z @ W1[64:128]
__device__ float  g_d[HID];                 // c @ W1[128:132] + b1
__device__ double g_sum[HID];
__device__ double g_sumsq[HID];
__device__ unsigned short g_Whi[16384];     // BN-folded W2 bf16-hi, MMA swizzled layout (32KB)
__device__ unsigned short g_Wlo[16384];     // bf16-lo residual
__device__ float2 g_w3b2[HID];              // (b2_folded, w3) per feature
__device__ int    g_is64;

// ---------------- helpers ----------------
__device__ __forceinline__ u32 smem_u32(const void* p) {
    u32 a;
    asm("{ .reg .u64 t; cvta.to.shared.u64 t, %1; cvt.u32.u64 %0, t; }" : "=r"(a) : "l"(p));
    return a;
}
// packed bf16x2 convert: low half <- lo, high half <- hi
__device__ __forceinline__ u32 bf2(float lo, float hi) {
    u32 r;
    asm("cvt.rn.bf16x2.f32 %0, %1, %2;" : "=r"(r) : "f"(hi), "f"(lo));
    return r;
}
__device__ __forceinline__ void ldsm4(u32* r, u32 addr) {
    asm volatile("ldmatrix.sync.aligned.m8n8.x4.shared.b16 {%0,%1,%2,%3}, [%4];"
                 : "=r"(r[0]), "=r"(r[1]), "=r"(r[2]), "=r"(r[3]) : "r"(addr));
}
__device__ __forceinline__ void mma16816(float* c, const u32* a, u32 b0, u32 b1) {
    asm volatile(
        "mma.sync.aligned.m16n8k16.row.col.f32.bf16.bf16.f32 "
        "{%0,%1,%2,%3}, {%4,%5,%6,%7}, {%8,%9}, {%0,%1,%2,%3};"
        : "+f"(c[0]), "+f"(c[1]), "+f"(c[2]), "+f"(c[3])
        : "r"(a[0]), "r"(a[1]), "r"(a[2]), "r"(a[3]), "r"(b0), "r"(b1));
}

// MMA-layout byte offset for element (row r, col k) in a 128x128 bf16 K-major
// SW128 blocked-atom tile: atom = 8 rows x 64 bf16 (1024B), 16 atom-rows x 2 atom-cols.
__device__ __forceinline__ int bofs(int r, int k) {
    int off = ((r >> 3) << 10) + ((k >> 6) << 14) + ((r & 7) << 7) + ((k & 63) << 1);
    return off ^ ((off >> 3) & 0x70);
}

// ---------------- K_detect: is edge_index int64 or int32? ----------------
__global__ void k_detect(const unsigned int* __restrict__ w) {
    __shared__ int nz;
    int t = threadIdx.x;
    if (t == 0) nz = 0;
    __syncthreads();
    if (w[2 * t + 1] != 0u) atomicAdd(&nz, 1);
    __syncthreads();
    if (t == 0) g_is64 = (nz == 0) ? 1 : 0;
}

// ---------------- K0: per-node partial products ----------------
__global__ void k0_nodes(const float* __restrict__ z, const float* __restrict__ W1, int N) {
    __shared__ float zs[NPB * ZD];
    int tid  = threadIdx.x;
    int base = blockIdx.x * NPB;
    int nn   = N - base; if (nn > NPB) nn = NPB;

    for (int i = tid; i < nn * ZD; i += 128) zs[i] = z[base * ZD + i];
    __syncthreads();

    float a[NPB], b[NPB];
#pragma unroll
    for (int n = 0; n < NPB; n++) { a[n] = 0.f; b[n] = 0.f; }

#pragma unroll 8
    for (int k = 0; k < ZD; k++) {
        float ws = W1[k * HID + tid];
        float wd = W1[(ZD + k) * HID + tid];
#pragma unroll
        for (int n = 0; n < NPB; n++) {
            float zk = zs[n * ZD + k];
            a[n] = fmaf(zk, ws, a[n]);
            b[n] = fmaf(zk, wd, b[n]);
        }
    }
    for (int n = 0; n < nn; n++) {
        g_A[(base + n) * HID + tid] = a[n];
        g_B[(base + n) * HID + tid] = b[n];
    }
}

// ---------------- K0b ----------------
__global__ void k0b_init(const float* __restrict__ c, const float* __restrict__ W1,
                         const float* __restrict__ b1) {
    int j = threadIdx.x;
    float v = b1[j];
#pragma unroll
    for (int k = 0; k < 4; k++) v = fmaf(c[k], W1[(2 * ZD + k) * HID + j], v);
    g_d[j]     = v;
    g_sum[j]   = 0.0;
    g_sumsq[j] = 0.0;
}

// ---------------- K1: BN statistics pass ----------------
template<bool IS64>
__device__ __forceinline__ int ldi(const void* ei, long long pos) {
    return IS64 ? (int)((const long long*)ei)[pos] : ((const int*)ei)[pos];
}

template<bool IS64>
__device__ __forceinline__ void k1_body(const void* __restrict__ ei, int E) {
    int j = threadIdx.x;
    float dreg = g_d[j];

    int per = (E + gridDim.x - 1) / (int)gridDim.x;
    int e0 = blockIdx.x * per;
    int e1 = e0 + per; if (e1 > E) e1 = E;

    float s1 = 0.f, s2 = 0.f;
    int e = e0;
    for (; e + 8 <= e1; e += 8) {
        int s[8], t[8];
#pragma unroll
        for (int i = 0; i < 8; i++) s[i] = ldi<IS64>(ei, e + i);
#pragma unroll
        for (int i = 0; i < 8; i++) t[i] = ldi<IS64>(ei, (long long)E + e + i);
        float av[8], bv[8];
#pragma unroll
        for (int i = 0; i < 8; i++) { av[i] = g_A[s[i] * HID + j]; bv[i] = g_B[t[i] * HID + j]; }
#pragma unroll
        for (int i = 0; i < 8; i++) {
            float h = fmaxf(av[i] + bv[i] + dreg, 0.f);
            s1 += h; s2 = fmaf(h, h, s2);
        }
    }
    for (; e < e1; e++) {
        int s = ldi<IS64>(ei, e);
        int t = ldi<IS64>(ei, (long long)E + e);
        float h = fmaxf(g_A[s * HID + j] + g_B[t * HID + j] + dreg, 0.f);
        s1 += h; s2 = fmaf(h, h, s2);
    }
    atomicAdd(&g_sum[j],   (double)s1);
    atomicAdd(&g_sumsq[j], (double)s2);
}

__global__ void k1_stats(const void* __restrict__ ei, int E) {
    if (g_is64) k1_body<true>(ei, E);
    else        k1_body<false>(ei, E);
}

// ---------------- K1.5: fold BN into W2 -> bf16 hi/lo in MMA swizzled layout ----------------
__global__ void k15_fold(const float* __restrict__ gamma, const float* __restrict__ beta,
                         const float* __restrict__ W2, const float* __restrict__ b2,
                         const float* __restrict__ W3, double invE) {
    __shared__ float gsc[HID], gsh[HID];
    int i = threadIdx.x;   // output feature f of layer 2

    double m = g_sum[i] * invE;
    double v = g_sumsq[i] * invE - m * m;
    float x = (float)v + 1e-5f;
    float s = rsqrtf(x);
    s = s * (1.5f - 0.5f * x * s * s);  // Newton refine
    float g = s * gamma[i];
    gsc[i] = g;
    gsh[i] = beta[i] - (float)m * g;
    __syncthreads();

    float bb = b2[i];
    for (int k = 0; k < HID; k++) {
        float w = W2[k * HID + i];           // W2[k][f=i]
        float wf = gsc[k] * w;               // BN scale folded (per input k)
        __nv_bfloat16 hb = __float2bfloat16(wf);
        float hf = __bfloat162float(hb);
        __nv_bfloat16 lb = __float2bfloat16(wf - hf);
        int o = bofs(i, k) >> 1;             // row = feature f, col = k
        g_Whi[o] = *(const unsigned short*)&hb;
        g_Wlo[o] = *(const unsigned short*)&lb;
        bb = fmaf(gsh[k], w, bb);
    }
    g_w3b2[i] = make_float2(bb, W3[i]);
}

// ---------------- K2: mma.sync bf16 fused gather + GEMM2 + ReLU + W3 dot ----------------
// smem (1024-aligned base):
#define OFF_WHI 0
#define OFF_WLO 32768
#define OFF_HHI 65536
#define OFF_HLO 98304
#define OFF_SD  131072          // d[128] floats
#define OFF_SRED 131584         // sred[4][128] floats
#define K2_SMEM (133632 + 1024)

__global__ void __launch_bounds__(256, 1)
k2_main(const void* __restrict__ ei, const float* __restrict__ b3,
        float* __restrict__ out, int E, int ntiles) {
    extern __shared__ char dsm[];
    u32 braw = smem_u32(dsm);
    u32 base = (braw + 1023u) & ~1023u;
    char* sm = dsm + (base - braw);

    int tid  = threadIdx.x;
    int wid  = tid >> 5, lane = tid & 31;
    int wm   = wid >> 2, wn = wid & 3;       // 2 row-halves x 4 feat-slices
    int li   = lane & 7, grp = lane >> 3;
    int is64 = g_is64;
    const long long* p64 = (const long long*)ei;
    const int*       p32 = (const int*)ei;

    float* sd   = (float*)(sm + OFF_SD);
    float* sred = (float*)(sm + OFF_SRED);

    // stage W2' bf16 hi/lo + d into smem
    {
        uint4* dh = (uint4*)(sm + OFF_WHI);
        uint4* dl = (uint4*)(sm + OFF_WLO);
        const uint4* shi = (const uint4*)g_Whi;
        const uint4* slo = (const uint4*)g_Wlo;
        for (int i = tid; i < 2048; i += 256) { dh[i] = shi[i]; dl[i] = slo[i]; }
        if (tid < HID) sd[tid] = g_d[tid];
    }

    // per-thread epilogue constants: 8 cols = {32*wn + nt*8 + 2*(lane&3) + cp}
    float2 wb[8];
#pragma unroll
    for (int nt = 0; nt < 4; nt++)
#pragma unroll
        for (int cp = 0; cp < 2; cp++)
            wb[nt * 2 + cp] = g_w3b2[32 * wn + nt * 8 + 2 * (lane & 3) + cp];
    float bias3 = b3[0];

    // fixed shared-addr components
    u32 wHiB = base + OFF_WHI, wLoB = base + OFF_WLO;
    u32 hHiB = base + OFF_HHI, hLoB = base + OFF_HLO;
    int kgA = (grp >> 1) * 8;                 // A frag k sub-offset
    int kgB = (grp & 1) * 8;                  // B frag k sub-offset
    int nB0 = 32 * wn + (grp >> 1) * 8 + li;  // B frag rows (feature index)
    int nB1 = nB0 + 16;
    int bq0 = ((nB0 >> 3) << 10) + ((nB0 & 7) << 7);
    int bq1 = ((nB1 >> 3) << 10) + ((nB1 & 7) << 7);

    // transform indexing: row = tid&127, k-half = tid>>7
    int trow = tid & 127, tkh = tid >> 7;

    __syncthreads();

    for (int tile = blockIdx.x; tile < ntiles; tile += gridDim.x) {
        // ---- transform: gather + relu + bf16 hi/lo split into swizzled smem ----
        {
            long long ge = (long long)tile * TM + trow;
            int s = 0, t = 0;
            if (ge < E) {
                s = is64 ? (int)p64[ge] : p32[ge];
                t = is64 ? (int)p64[(long long)E + ge] : p32[(long long)E + ge];
            }
            const float4* ap = (const float4*)(g_A + (size_t)s * HID) + tkh * 16;
            const float4* bp = (const float4*)(g_B + (size_t)t * HID) + tkh * 16;
            const float4* dp = (const float4*)sd + tkh * 16;
            char* aHi = sm + OFF_HHI;
            char* aLo = sm + OFF_HLO;
#pragma unroll 4
            for (int i = 0; i < 16; i += 2) {
                float4 a0 = ap[i], a1 = ap[i + 1];
                float4 b0 = bp[i], b1 = bp[i + 1];
                float4 d0 = dp[i], d1 = dp[i + 1];
                float h[8];
                h[0] = fmaxf(a0.x + b0.x + d0.x, 0.f);
                h[1] = fmaxf(a0.y + b0.y + d0.y, 0.f);
                h[2] = fmaxf(a0.z + b0.z + d0.z, 0.f);
                h[3] = fmaxf(a0.w + b0.w + d0.w, 0.f);
                h[4] = fmaxf(a1.x + b1.x + d1.x, 0.f);
                h[5] = fmaxf(a1.y + b1.y + d1.y, 0.f);
                h[6] = fmaxf(a1.z + b1.z + d1.z, 0.f);
                h[7] = fmaxf(a1.w + b1.w + d1.w, 0.f);
                u32 uh[4], ul[4];
#pragma unroll
                for (int j = 0; j < 4; j++) {
                    u32 ph = bf2(h[2 * j], h[2 * j + 1]);
                    float r0 = __uint_as_float(ph << 16);
                    float r1 = __uint_as_float(ph & 0xFFFF0000u);
                    uh[j] = ph;
                    ul[j] = bf2(h[2 * j] - r0, h[2 * j + 1] - r1);
                }
                int o = bofs(trow, tkh * 64 + i * 4);
                *(uint4*)(aHi + o) = make_uint4(uh[0], uh[1], uh[2], uh[3]);
                *(uint4*)(aLo + o) = make_uint4(ul[0], ul[1], ul[2], ul[3]);
            }
        }
        __syncthreads();  // H ready; prev tile's sred consumed

        // ---- MMA: 2 chunks of 32 rows, 3 bf16 passes, 8 k-steps ----
#pragma unroll 1
        for (int c = 0; c < 2; c++) {
            int mr = wm * 64 + c * 32;
            int rA0 = mr + (grp & 1) * 8 + li;
            int rp0 = ((rA0 >> 3) << 10) + ((rA0 & 7) << 7);
            int rA1 = rA0 + 16;
            int rp1 = ((rA1 >> 3) << 10) + ((rA1 & 7) << 7);

            float acc[2][4][4];
#pragma unroll
            for (int mt = 0; mt < 2; mt++)
#pragma unroll
                for (int nt = 0; nt < 4; nt++)
#pragma unroll
                    for (int q = 0; q < 4; q++) acc[mt][nt][q] = 0.f;

#pragma unroll 1
            for (int pass = 0; pass < 3; pass++) {
                u32 Ab = (pass == 2) ? hLoB : hHiB;
                u32 Bb = (pass == 1) ? wLoB : wHiB;
#pragma unroll
                for (int ks = 0; ks < 8; ks++) {
                    int k0 = ks * 16;
                    int kkA = k0 + kgA;
                    int kpA = ((kkA >> 6) << 14) + ((kkA & 63) << 1);
                    int oA0 = rp0 + kpA; oA0 ^= ((oA0 >> 3) & 0x70);
                    int oA1 = rp1 + kpA; oA1 ^= ((oA1 >> 3) & 0x70);
                    int kkB = k0 + kgB;
                    int kpB = ((kkB >> 6) << 14) + ((kkB & 63) << 1);
                    int oB0 = bq0 + kpB; oB0 ^= ((oB0 >> 3) & 0x70);
                    int oB1 = bq1 + kpB; oB1 ^= ((oB1 >> 3) & 0x70);

                    u32 af0[4], af1[4], bf0[4], bf1[4];
                    ldsm4(af0, Ab + (u32)oA0);
                    ldsm4(af1, Ab + (u32)oA1);
                    ldsm4(bf0, Bb + (u32)oB0);
                    ldsm4(bf1, Bb + (u32)oB1);

                    mma16816(acc[0][0], af0, bf0[0], bf0[1]);
                    mma16816(acc[0][1], af0, bf0[2], bf0[3]);
                    mma16816(acc[0][2], af0, bf1[0], bf1[1]);
                    mma16816(acc[0][3], af0, bf1[2], bf1[3]);
                    mma16816(acc[1][0], af1, bf0[0], bf0[1]);
                    mma16816(acc[1][1], af1, bf0[2], bf0[3]);
                    mma16816(acc[1][2], af1, bf1[0], bf1[1]);
                    mma16816(acc[1][3], af1, bf1[2], bf1[3]);
                }
            }

            // ---- epilogue: relu(acc + b2') . w3, quad-reduce, stash per-warp partial ----
#pragma unroll
            for (int mt = 0; mt < 2; mt++) {
                float pl = 0.f, ph = 0.f;
#pragma unroll
                for (int nt = 0; nt < 4; nt++)
#pragma unroll
                    for (int cp = 0; cp < 2; cp++) {
                        float2 w = wb[nt * 2 + cp];
                        pl = fmaf(fmaxf(acc[mt][nt][cp]     + w.x, 0.f), w.y, pl);
                        ph = fmaf(fmaxf(acc[mt][nt][2 + cp] + w.x, 0.f), w.y, ph);
                    }
                pl += __shfl_xor_sync(0xffffffffu, pl, 1);
                pl += __shfl_xor_sync(0xffffffffu, pl, 2);
                ph += __shfl_xor_sync(0xffffffffu, ph, 1);
                ph += __shfl_xor_sync(0xffffffffu, ph, 2);
                if ((lane & 3) == 0) {
                    int r = mr + mt * 16 + (lane >> 2);
                    sred[wn * 128 + r]     = pl;
                    sred[wn * 128 + r + 8] = ph;
                }
            }
        }
        __syncthreads();  // sred ready; all H reads done

        // ---- final cross-warp sum + store ----
        if (tid < TM) {
            long long ge = (long long)tile * TM + tid;
            if (ge < E) {
                float v = sred[tid] + sred[128 + tid] + sred[256 + tid] + sred[384 + tid];
                out[ge] = v + bias3;
            }
        }
    }
}

// ---------------- launch ----------------
extern "C" void kernel_launch(void* const* d_in, const int* in_sizes, int n_in,
                              void* d_out, int out_size) {
    const float* z     = (const float*)d_in[0];
    const void*  ei    = d_in[1];
    const float* c     = (const float*)d_in[2];
    const float* W1    = (const float*)d_in[3];
    const float* b1    = (const float*)d_in[4];
    const float* gamma = (const float*)d_in[5];
    const float* beta  = (const float*)d_in[6];
    const float* W2    = (const float*)d_in[7];
    const float* b2    = (const float*)d_in[8];
    const float* W3    = (const float*)d_in[9];
    const float* b3    = (const float*)d_in[10];
    float* out = (float*)d_out;

    int N = in_sizes[0] / ZD;
    int E = in_sizes[1] / 2;

    cudaFuncSetAttribute(k2_main, cudaFuncAttributeMaxDynamicSharedMemorySize, K2_SMEM);

    k_detect<<<1, 128>>>((const unsigned int*)ei);
    k0_nodes<<<(N + NPB - 1) / NPB, 128>>>(z, W1, N);
    k0b_init<<<1, 128>>>(c, W1, b1);
    k1_stats<<<K1_BLOCKS, 128>>>(ei, E);
    k15_fold<<<1, 128>>>(gamma, beta, W2, b2, W3, 1.0 / (double)E);
    int ntiles = (E + TM - 1) / TM;
    k2_main<<<K2_GRID, 256, K2_SMEM>>>(ei, b3, out, E, ntiles);
}

// round 6
// speedup vs baseline: 2.0983x; 1.0350x over previous
#include <cuda_runtime.h>
#include <cuda_bf16.h>
#include <stdint.h>

#define NODES_MAX 50000
#define HID 128
#define ZD 64
#define NPB 16          // nodes per block in K0
#define TM 128          // edges per tile in K2
#define K1_BLOCKS 1184  // 148 SMs * 8
#define K2_GRID 148

typedef unsigned long long u64;
typedef unsigned int u32;

// ---------------- static device scratch ----------------
__device__ float  g_A[NODES_MAX * HID];     // z @ W1[0:64]
__device__ float  g_B[NODES_MAX * HID];     // z @ W1[64:128]
__device__ float  g_d[HID];                 // c @ W1[128:132] + b1
__device__ double g_sum[HID];
__device__ double g_sumsq[HID];
__device__ unsigned short g_Whi[16384];     // BN-folded W2 bf16-hi, MMA swizzled layout
__device__ unsigned short g_Wlo[16384];     // bf16-lo residual
__device__ float2 g_w3b2[HID];              // (b2_folded, w3) per feature
__device__ int    g_is64;

// ---------------- helpers ----------------
__device__ __forceinline__ u32 smem_u32(const void* p) {
    u32 a;
    asm("{ .reg .u64 t; cvta.to.shared.u64 t, %1; cvt.u32.u64 %0, t; }" : "=r"(a) : "l"(p));
    return a;
}
// packed bf16x2 convert: low half <- lo, high half <- hi
__device__ __forceinline__ u32 bf2(float lo, float hi) {
    u32 r;
    asm("cvt.rn.bf16x2.f32 %0, %1, %2;" : "=r"(r) : "f"(hi), "f"(lo));
    return r;
}
__device__ __forceinline__ void ldsm4(u32* r, u32 addr) {
    asm volatile("ldmatrix.sync.aligned.m8n8.x4.shared.b16 {%0,%1,%2,%3}, [%4];"
                 : "=r"(r[0]), "=r"(r[1]), "=r"(r[2]), "=r"(r[3]) : "r"(addr));
}
__device__ __forceinline__ void mma16816(float* c, const u32* a, u32 b0, u32 b1) {
    asm volatile(
        "mma.sync.aligned.m16n8k16.row.col.f32.bf16.bf16.f32 "
        "{%0,%1,%2,%3}, {%4,%5,%6,%7}, {%8,%9}, {%0,%1,%2,%3};"
        : "+f"(c[0]), "+f"(c[1]), "+f"(c[2]), "+f"(c[3])
        : "r"(a[0]), "r"(a[1]), "r"(a[2]), "r"(a[3]), "r"(b0), "r"(b1));
}

// MMA-layout byte offset for element (row r, col k) in a 128x128 bf16 K-major
// SW128 blocked-atom tile: atom = 8 rows x 64 bf16 (1024B), 16 atom-rows x 2 atom-cols.
__device__ __forceinline__ int bofs(int r, int k) {
    int off = ((r >> 3) << 10) + ((k >> 6) << 14) + ((r & 7) << 7) + ((k & 63) << 1);
    return off ^ ((off >> 3) & 0x70);
}

// ---------------- K0: per-node partial products (+fused detect & k0b in extra block) ----------------
__global__ void k0_nodes(const float* __restrict__ z, const float* __restrict__ W1, int N,
                         const unsigned int* __restrict__ eiw,
                         const float* __restrict__ c, const float* __restrict__ b1) {
    __shared__ float zs[NPB * ZD];
    int tid = threadIdx.x;

    if (blockIdx.x == gridDim.x - 1) {
        // --- fused k_detect: is edge_index int64 or int32? ---
        __shared__ int nz;
        if (tid == 0) nz = 0;
        __syncthreads();
        if (eiw[2 * tid + 1] != 0u) atomicAdd(&nz, 1);
        __syncthreads();
        if (tid == 0) g_is64 = (nz == 0) ? 1 : 0;
        // --- fused k0b: d = c@W1c + b1, zero BN accumulators ---
        float v = b1[tid];
#pragma unroll
        for (int k = 0; k < 4; k++) v = fmaf(c[k], W1[(2 * ZD + k) * HID + tid], v);
        g_d[tid]     = v;
        g_sum[tid]   = 0.0;
        g_sumsq[tid] = 0.0;
        return;
    }

    int base = blockIdx.x * NPB;
    int nn   = N - base; if (nn > NPB) nn = NPB;

    for (int i = tid; i < nn * ZD; i += 128) zs[i] = z[base * ZD + i];
    __syncthreads();

    float a[NPB], b[NPB];
#pragma unroll
    for (int n = 0; n < NPB; n++) { a[n] = 0.f; b[n] = 0.f; }

#pragma unroll 8
    for (int k = 0; k < ZD; k++) {
        float ws = W1[k * HID + tid];
        float wd = W1[(ZD + k) * HID + tid];
#pragma unroll
        for (int n = 0; n < NPB; n++) {
            float zk = zs[n * ZD + k];
            a[n] = fmaf(zk, ws, a[n]);
            b[n] = fmaf(zk, wd, b[n]);
        }
    }
    for (int n = 0; n < nn; n++) {
        g_A[(base + n) * HID + tid] = a[n];
        g_B[(base + n) * HID + tid] = b[n];
    }
}

// ---------------- K1: BN statistics pass ----------------
template<bool IS64>
__device__ __forceinline__ int ldi(const void* ei, long long pos) {
    return IS64 ? (int)((const long long*)ei)[pos] : ((const int*)ei)[pos];
}

template<bool IS64>
__device__ __forceinline__ void k1_body(const void* __restrict__ ei, int E) {
    int j = threadIdx.x;
    float dreg = g_d[j];

    int per = (E + gridDim.x - 1) / (int)gridDim.x;
    int e0 = blockIdx.x * per;
    int e1 = e0 + per; if (e1 > E) e1 = E;

    float s1 = 0.f, s2 = 0.f;
    int e = e0;
    for (; e + 8 <= e1; e += 8) {
        int s[8], t[8];
#pragma unroll
        for (int i = 0; i < 8; i++) s[i] = ldi<IS64>(ei, e + i);
#pragma unroll
        for (int i = 0; i < 8; i++) t[i] = ldi<IS64>(ei, (long long)E + e + i);
        float av[8], bv[8];
#pragma unroll
        for (int i = 0; i < 8; i++) { av[i] = g_A[s[i] * HID + j]; bv[i] = g_B[t[i] * HID + j]; }
#pragma unroll
        for (int i = 0; i < 8; i++) {
            float h = fmaxf(av[i] + bv[i] + dreg, 0.f);
            s1 += h; s2 = fmaf(h, h, s2);
        }
    }
    for (; e < e1; e++) {
        int s = ldi<IS64>(ei, e);
        int t = ldi<IS64>(ei, (long long)E + e);
        float h = fmaxf(g_A[s * HID + j] + g_B[t * HID + j] + dreg, 0.f);
        s1 += h; s2 = fmaf(h, h, s2);
    }
    atomicAdd(&g_sum[j],   (double)s1);
    atomicAdd(&g_sumsq[j], (double)s2);
}

__global__ void k1_stats(const void* __restrict__ ei, int E) {
    if (g_is64) k1_body<true>(ei, E);
    else        k1_body<false>(ei, E);
}

// ---------------- K1.5: fold BN into W2 -> bf16 hi/lo in MMA swizzled layout ----------------
__global__ void k15_fold(const float* __restrict__ gamma, const float* __restrict__ beta,
                         const float* __restrict__ W2, const float* __restrict__ b2,
                         const float* __restrict__ W3, double invE) {
    __shared__ float gsc[HID], gsh[HID];
    int i = threadIdx.x;   // output feature f of layer 2

    double m = g_sum[i] * invE;
    double v = g_sumsq[i] * invE - m * m;
    float x = (float)v + 1e-5f;
    float s = rsqrtf(x);
    s = s * (1.5f - 0.5f * x * s * s);  // Newton refine
    float g = s * gamma[i];
    gsc[i] = g;
    gsh[i] = beta[i] - (float)m * g;
    __syncthreads();

    float bb = b2[i];
    for (int k = 0; k < HID; k++) {
        float w = W2[k * HID + i];           // W2[k][f=i]
        float wf = gsc[k] * w;               // BN scale folded (per input k)
        __nv_bfloat16 hb = __float2bfloat16(wf);
        float hf = __bfloat162float(hb);
        __nv_bfloat16 lb = __float2bfloat16(wf - hf);
        int o = bofs(i, k) >> 1;             // row = feature f, col = k
        g_Whi[o] = *(const unsigned short*)&hb;
        g_Wlo[o] = *(const unsigned short*)&lb;
        bb = fmaf(gsh[k], w, bb);
    }
    g_w3b2[i] = make_float2(bb, W3[i]);
}

// ---------------- K2: warp-specialized producer/consumer ----------------
// 384 threads: warps 0-7 = MMA consumers, warps 8-11 = gather/transform producers.
// smem (1024-aligned base):
#define OFF_WHI 0
#define OFF_WLO 32768
#define OFF_H(buf, part) (65536 + (buf) * 65536 + (part) * 32768)
#define OFF_SD  196608          // d[128] floats
#define OFF_SRED 197120         // sred[4][128] floats
#define K2_SMEM (199168 + 1024)

// producer: gather + relu + bf16 hi/lo split for edge-row r of `tile` into H[buf]
static __device__ __forceinline__ void k2_produce(
    int tile, long long E, int is64, const long long* p64, const int* p32,
    const float* sd, char* aHi, char* aLo, int r)
{
    long long ge = (long long)tile * TM + r;
    int s = 0, t = 0;
    if (ge < E) {
        s = is64 ? (int)p64[ge] : p32[ge];
        t = is64 ? (int)p64[E + ge] : p32[E + ge];
    }
    const float4* apb = (const float4*)(g_A + (size_t)s * HID);
    const float4* bpb = (const float4*)(g_B + (size_t)t * HID);
    const float4* dpb = (const float4*)sd;
#pragma unroll 2
    for (int half = 0; half < 2; half++) {
        const float4* ap = apb + half * 16;
        const float4* bp = bpb + half * 16;
        const float4* dp = dpb + half * 16;
#pragma unroll 4
        for (int i = 0; i < 16; i += 2) {
            float4 a0 = ap[i], a1 = ap[i + 1];
            float4 b0 = bp[i], b1 = bp[i + 1];
            float4 d0 = dp[i], d1 = dp[i + 1];
            float h[8];
            h[0] = fmaxf(a0.x + b0.x + d0.x, 0.f);
            h[1] = fmaxf(a0.y + b0.y + d0.y, 0.f);
            h[2] = fmaxf(a0.z + b0.z + d0.z, 0.f);
            h[3] = fmaxf(a0.w + b0.w + d0.w, 0.f);
            h[4] = fmaxf(a1.x + b1.x + d1.x, 0.f);
            h[5] = fmaxf(a1.y + b1.y + d1.y, 0.f);
            h[6] = fmaxf(a1.z + b1.z + d1.z, 0.f);
            h[7] = fmaxf(a1.w + b1.w + d1.w, 0.f);
            u32 uh[4], ul[4];
#pragma unroll
            for (int j = 0; j < 4; j++) {
                u32 ph = bf2(h[2 * j], h[2 * j + 1]);
                float r0 = __uint_as_float(ph << 16);
                float r1 = __uint_as_float(ph & 0xFFFF0000u);
                uh[j] = ph;
                ul[j] = bf2(h[2 * j] - r0, h[2 * j + 1] - r1);
            }
            int o = bofs(r, half * 64 + i * 4);
            *(uint4*)(aHi + o) = make_uint4(uh[0], uh[1], uh[2], uh[3]);
            *(uint4*)(aLo + o) = make_uint4(ul[0], ul[1], ul[2], ul[3]);
        }
    }
}

__global__ void __launch_bounds__(384, 1)
k2_main(const void* __restrict__ ei, const float* __restrict__ b3,
        float* __restrict__ out, int E, int ntiles) {
    extern __shared__ char dsm[];
    u32 braw = smem_u32(dsm);
    u32 base = (braw + 1023u) & ~1023u;
    char* sm = dsm + (base - braw);

    int tid  = threadIdx.x;
    int wid  = tid >> 5, lane = tid & 31;
    int is64 = g_is64;
    const long long* p64 = (const long long*)ei;
    const int*       p32 = (const int*)ei;

    float* sd   = (float*)(sm + OFF_SD);
    float* sred = (float*)(sm + OFF_SRED);

    // stage W2' bf16 hi/lo + d into smem (all 384 threads)
    {
        uint4* dh = (uint4*)(sm + OFF_WHI);
        uint4* dl = (uint4*)(sm + OFF_WLO);
        const uint4* shi = (const uint4*)g_Whi;
        const uint4* slo = (const uint4*)g_Wlo;
        for (int i = tid; i < 2048; i += 384) { dh[i] = shi[i]; dl[i] = slo[i]; }
        if (tid < HID) sd[tid] = g_d[tid];
    }
    float bias3 = b3[0];
    u32 wHiB = base + OFF_WHI, wLoB = base + OFF_WLO;

    // consumer-only constants
    int wm = (wid >> 2) & 1, wn = wid & 3;
    int li = lane & 7, grp = lane >> 3;
    float2 wb[8];
#pragma unroll
    for (int nt = 0; nt < 4; nt++)
#pragma unroll
        for (int cp = 0; cp < 2; cp++)
            wb[nt * 2 + cp] = g_w3b2[32 * wn + nt * 8 + 2 * (lane & 3) + cp];
    int kgA = (grp >> 1) * 8;
    int kgB = (grp & 1) * 8;
    int nB0 = 32 * wn + (grp >> 1) * 8 + li;
    int nB1 = nB0 + 16;
    int bq0 = ((nB0 >> 3) << 10) + ((nB0 & 7) << 7);
    int bq1 = ((nB1 >> 3) << 10) + ((nB1 & 7) << 7);

    __syncthreads();  // W, sd staged

    // prologue: producers fill buf0 with this block's first tile
    int first = blockIdx.x;
    if (wid >= 8 && first < ntiles)
        k2_produce(first, E, is64, p64, p32, sd,
                   sm + OFF_H(0, 0), sm + OFF_H(0, 1), tid - 256);

    int iter = 0;
    for (int tile = first; tile < ntiles; tile += gridDim.x, iter++) {
        int buf = iter & 1;
        __syncthreads();  // H[buf] ready; H[buf^1] free

        if (wid < 8) {
            // ================= CONSUMERS: MMA on H[buf] =================
            u32 hHiB = base + OFF_H(buf, 0);
            u32 hLoB = base + OFF_H(buf, 1);
#pragma unroll 1
            for (int c = 0; c < 2; c++) {
                int mr = wm * 64 + c * 32;
                int rA0 = mr + (grp & 1) * 8 + li;
                int rp0 = ((rA0 >> 3) << 10) + ((rA0 & 7) << 7);
                int rA1 = rA0 + 16;
                int rp1 = ((rA1 >> 3) << 10) + ((rA1 & 7) << 7);

                float acc[2][4][4];
#pragma unroll
                for (int mt = 0; mt < 2; mt++)
#pragma unroll
                    for (int nt = 0; nt < 4; nt++)
#pragma unroll
                        for (int q = 0; q < 4; q++) acc[mt][nt][q] = 0.f;

#pragma unroll 1
                for (int pass = 0; pass < 3; pass++) {
                    u32 Ab = (pass == 2) ? hLoB : hHiB;
                    u32 Bb = (pass == 1) ? wLoB : wHiB;
#pragma unroll
                    for (int ks = 0; ks < 8; ks++) {
                        int k0 = ks * 16;
                        int kkA = k0 + kgA;
                        int kpA = ((kkA >> 6) << 14) + ((kkA & 63) << 1);
                        int oA0 = rp0 + kpA; oA0 ^= ((oA0 >> 3) & 0x70);
                        int oA1 = rp1 + kpA; oA1 ^= ((oA1 >> 3) & 0x70);
                        int kkB = k0 + kgB;
                        int kpB = ((kkB >> 6) << 14) + ((kkB & 63) << 1);
                        int oB0 = bq0 + kpB; oB0 ^= ((oB0 >> 3) & 0x70);
                        int oB1 = bq1 + kpB; oB1 ^= ((oB1 >> 3) & 0x70);

                        u32 af0[4], af1[4], bf0[4], bf1[4];
                        ldsm4(af0, Ab + (u32)oA0);
                        ldsm4(af1, Ab + (u32)oA1);
                        ldsm4(bf0, Bb + (u32)oB0);
                        ldsm4(bf1, Bb + (u32)oB1);

                        mma16816(acc[0][0], af0, bf0[0], bf0[1]);
                        mma16816(acc[0][1], af0, bf0[2], bf0[3]);
                        mma16816(acc[0][2], af0, bf1[0], bf1[1]);
                        mma16816(acc[0][3], af0, bf1[2], bf1[3]);
                        mma16816(acc[1][0], af1, bf0[0], bf0[1]);
                        mma16816(acc[1][1], af1, bf0[2], bf0[3]);
                        mma16816(acc[1][2], af1, bf1[0], bf1[1]);
                        mma16816(acc[1][3], af1, bf1[2], bf1[3]);
                    }
                }

                // epilogue: relu(acc + b2') . w3, quad-reduce, stash per-warp partial
#pragma unroll
                for (int mt = 0; mt < 2; mt++) {
                    float pl = 0.f, ph = 0.f;
#pragma unroll
                    for (int nt = 0; nt < 4; nt++)
#pragma unroll
                        for (int cp = 0; cp < 2; cp++) {
                            float2 w = wb[nt * 2 + cp];
                            pl = fmaf(fmaxf(acc[mt][nt][cp]     + w.x, 0.f), w.y, pl);
                            ph = fmaf(fmaxf(acc[mt][nt][2 + cp] + w.x, 0.f), w.y, ph);
                        }
                    pl += __shfl_xor_sync(0xffffffffu, pl, 1);
                    pl += __shfl_xor_sync(0xffffffffu, pl, 2);
                    ph += __shfl_xor_sync(0xffffffffu, ph, 1);
                    ph += __shfl_xor_sync(0xffffffffu, ph, 2);
                    if ((lane & 3) == 0) {
                        int r = mr + mt * 16 + (lane >> 2);
                        sred[wn * 128 + r]     = pl;
                        sred[wn * 128 + r + 8] = ph;
                    }
                }
            }
            // consumer-only barrier, then final cross-warp sum + store
            asm volatile("bar.sync 1, 256;" ::: "memory");
            if (tid < TM) {
                long long ge = (long long)tile * TM + tid;
                if (ge < E) {
                    float v = sred[tid] + sred[128 + tid] + sred[256 + tid] + sred[384 + tid];
                    out[ge] = v + bias3;
                }
            }
        } else {
            // ================= PRODUCERS: transform tile+grid into H[buf^1] =================
            int nt = tile + gridDim.x;
            if (nt < ntiles)
                k2_produce(nt, E, is64, p64, p32, sd,
                           sm + OFF_H(buf ^ 1, 0), sm + OFF_H(buf ^ 1, 1), tid - 256);
        }
    }
}

// ---------------- launch ----------------
extern "C" void kernel_launch(void* const* d_in, const int* in_sizes, int n_in,
                              void* d_out, int out_size) {
    const float* z     = (const float*)d_in[0];
    const void*  ei    = d_in[1];
    const float* c     = (const float*)d_in[2];
    const float* W1    = (const float*)d_in[3];
    const float* b1    = (const float*)d_in[4];
    const float* gamma = (const float*)d_in[5];
    const float* beta  = (const float*)d_in[6];
    const float* W2    = (const float*)d_in[7];
    const float* b2    = (const float*)d_in[8];
    const float* W3    = (const float*)d_in[9];
    const float* b3    = (const float*)d_in[10];
    float* out = (float*)d_out;

    int N = in_sizes[0] / ZD;
    int E = in_sizes[1] / 2;

    cudaFuncSetAttribute(k2_main, cudaFuncAttributeMaxDynamicSharedMemorySize, K2_SMEM);

    k0_nodes<<<(N + NPB - 1) / NPB + 1, 128>>>(z, W1, N, (const unsigned int*)ei, c, b1);
    k1_stats<<<K1_BLOCKS, 128>>>(ei, E);
    k15_fold<<<1, 128>>>(gamma, beta, W2, b2, W3, 1.0 / (double)E);
    int ntiles = (E + TM - 1) / TM;
    k2_main<<<K2_GRID, 384, K2_SMEM>>>(ei, b3, out, E, ntiles);
}

// round 7
// speedup vs baseline: 2.3715x; 1.1302x over previous
#include <cuda_runtime.h>
#include <cuda_bf16.h>
#include <stdint.h>

#define NODES_MAX 50000
#define HID 128
#define ZD 64
#define NPB 16          // nodes per block in K0
#define TM 128          // edges per tile in K2
#define K1_BLOCKS 1184  // 148 SMs * 8
#define K2_GRID 148

typedef unsigned long long u64;
typedef unsigned int u32;

// ---------------- static device scratch ----------------
__device__ float  g_A[NODES_MAX * HID];     // z @ W1[0:64]
__device__ float  g_B[NODES_MAX * HID];     // z @ W1[64:128]
__device__ float  g_d[HID];                 // c @ W1[128:132] + b1
__device__ double g_sum[HID];
__device__ double g_sumsq[HID];
__device__ unsigned short g_Whi[16384];     // BN-folded W2 bf16-hi, MMA swizzled layout
__device__ unsigned short g_Wlo[16384];     // bf16-lo residual
__device__ float2 g_w3b2[HID];              // (b2_folded, w3) per feature
__device__ int    g_is64;

// ---------------- helpers ----------------
__device__ __forceinline__ u32 smem_u32(const void* p) {
    u32 a;
    asm("{ .reg .u64 t; cvta.to.shared.u64 t, %1; cvt.u32.u64 %0, t; }" : "=r"(a) : "l"(p));
    return a;
}
// packed bf16x2 convert: low half <- lo, high half <- hi
__device__ __forceinline__ u32 bf2(float lo, float hi) {
    u32 r;
    asm("cvt.rn.bf16x2.f32 %0, %1, %2;" : "=r"(r) : "f"(hi), "f"(lo));
    return r;
}
__device__ __forceinline__ void ldsm4(u32* r, u32 addr) {
    asm volatile("ldmatrix.sync.aligned.m8n8.x4.shared.b16 {%0,%1,%2,%3}, [%4];"
                 : "=r"(r[0]), "=r"(r[1]), "=r"(r[2]), "=r"(r[3]) : "r"(addr));
}
__device__ __forceinline__ void mma16816(float* c, const u32* a, u32 b0, u32 b1) {
    asm volatile(
        "mma.sync.aligned.m16n8k16.row.col.f32.bf16.bf16.f32 "
        "{%0,%1,%2,%3}, {%4,%5,%6,%7}, {%8,%9}, {%0,%1,%2,%3};"
        : "+f"(c[0]), "+f"(c[1]), "+f"(c[2]), "+f"(c[3])
        : "r"(a[0]), "r"(a[1]), "r"(a[2]), "r"(a[3]), "r"(b0), "r"(b1));
}

// MMA-layout byte offset for element (row r, col k) in a 128x128 bf16 K-major
// SW128 blocked-atom tile: atom = 8 rows x 64 bf16 (1024B), 16 atom-rows x 2 atom-cols.
__device__ __forceinline__ int bofs(int r, int k) {
    int off = ((r >> 3) << 10) + ((k >> 6) << 14) + ((r & 7) << 7) + ((k & 63) << 1);
    return off ^ ((off >> 3) & 0x70);
}

// ---------------- K0: per-node partial products (+fused detect & k0b in extra block) ----------------
__global__ void k0_nodes(const float* __restrict__ z, const float* __restrict__ W1, int N,
                         const unsigned int* __restrict__ eiw,
                         const float* __restrict__ c, const float* __restrict__ b1) {
    __shared__ float zs[NPB * ZD];
    int tid = threadIdx.x;

    if (blockIdx.x == gridDim.x - 1) {
        // --- fused k_detect: is edge_index int64 or int32? ---
        __shared__ int nz;
        if (tid == 0) nz = 0;
        __syncthreads();
        if (eiw[2 * tid + 1] != 0u) atomicAdd(&nz, 1);
        __syncthreads();
        if (tid == 0) g_is64 = (nz == 0) ? 1 : 0;
        // --- fused k0b: d = c@W1c + b1, zero BN accumulators ---
        float v = b1[tid];
#pragma unroll
        for (int k = 0; k < 4; k++) v = fmaf(c[k], W1[(2 * ZD + k) * HID + tid], v);
        g_d[tid]     = v;
        g_sum[tid]   = 0.0;
        g_sumsq[tid] = 0.0;
        return;
    }

    int base = blockIdx.x * NPB;
    int nn   = N - base; if (nn > NPB) nn = NPB;

    for (int i = tid; i < nn * ZD; i += 128) zs[i] = z[base * ZD + i];
    __syncthreads();

    float a[NPB], b[NPB];
#pragma unroll
    for (int n = 0; n < NPB; n++) { a[n] = 0.f; b[n] = 0.f; }

#pragma unroll 8
    for (int k = 0; k < ZD; k++) {
        float ws = W1[k * HID + tid];
        float wd = W1[(ZD + k) * HID + tid];
#pragma unroll
        for (int n = 0; n < NPB; n++) {
            float zk = zs[n * ZD + k];
            a[n] = fmaf(zk, ws, a[n]);
            b[n] = fmaf(zk, wd, b[n]);
        }
    }
    for (int n = 0; n < nn; n++) {
        g_A[(base + n) * HID + tid] = a[n];
        g_B[(base + n) * HID + tid] = b[n];
    }
}

// ---------------- K1: BN statistics pass ----------------
template<bool IS64>
__device__ __forceinline__ int ldi(const void* ei, long long pos) {
    return IS64 ? (int)((const long long*)ei)[pos] : ((const int*)ei)[pos];
}

template<bool IS64>
__device__ __forceinline__ void k1_body(const void* __restrict__ ei, int E) {
    int j = threadIdx.x;
    float dreg = g_d[j];

    int per = (E + gridDim.x - 1) / (int)gridDim.x;
    int e0 = blockIdx.x * per;
    int e1 = e0 + per; if (e1 > E) e1 = E;

    float s1 = 0.f, s2 = 0.f;
    int e = e0;
    for (; e + 8 <= e1; e += 8) {
        int s[8], t[8];
#pragma unroll
        for (int i = 0; i < 8; i++) s[i] = ldi<IS64>(ei, e + i);
#pragma unroll
        for (int i = 0; i < 8; i++) t[i] = ldi<IS64>(ei, (long long)E + e + i);
        float av[8], bv[8];
#pragma unroll
        for (int i = 0; i < 8; i++) { av[i] = g_A[s[i] * HID + j]; bv[i] = g_B[t[i] * HID + j]; }
#pragma unroll
        for (int i = 0; i < 8; i++) {
            float h = fmaxf(av[i] + bv[i] + dreg, 0.f);
            s1 += h; s2 = fmaf(h, h, s2);
        }
    }
    for (; e < e1; e++) {
        int s = ldi<IS64>(ei, e);
        int t = ldi<IS64>(ei, (long long)E + e);
        float h = fmaxf(g_A[s * HID + j] + g_B[t * HID + j] + dreg, 0.f);
        s1 += h; s2 = fmaf(h, h, s2);
    }
    atomicAdd(&g_sum[j],   (double)s1);
    atomicAdd(&g_sumsq[j], (double)s2);
}

__global__ void k1_stats(const void* __restrict__ ei, int E) {
    if (g_is64) k1_body<true>(ei, E);
    else        k1_body<false>(ei, E);
}

// ---------------- K1.5: fold BN into W2 -> bf16 hi/lo in MMA swizzled layout ----------------
__global__ void k15_fold(const float* __restrict__ gamma, const float* __restrict__ beta,
                         const float* __restrict__ W2, const float* __restrict__ b2,
                         const float* __restrict__ W3, double invE) {
    __shared__ float gsc[HID], gsh[HID];
    int i = threadIdx.x;   // output feature f of layer 2

    double m = g_sum[i] * invE;
    double v = g_sumsq[i] * invE - m * m;
    float x = (float)v + 1e-5f;
    float s = rsqrtf(x);
    s = s * (1.5f - 0.5f * x * s * s);  // Newton refine
    float g = s * gamma[i];
    gsc[i] = g;
    gsh[i] = beta[i] - (float)m * g;
    __syncthreads();

    float bb = b2[i];
    for (int k = 0; k < HID; k++) {
        float w = W2[k * HID + i];           // W2[k][f=i]
        float wf = gsc[k] * w;               // BN scale folded (per input k)
        __nv_bfloat16 hb = __float2bfloat16(wf);
        float hf = __bfloat162float(hb);
        __nv_bfloat16 lb = __float2bfloat16(wf - hf);
        int o = bofs(i, k) >> 1;             // row = feature f, col = k
        g_Whi[o] = *(const unsigned short*)&hb;
        g_Wlo[o] = *(const unsigned short*)&lb;
        bb = fmaf(gsh[k], w, bb);
    }
    g_w3b2[i] = make_float2(bb, W3[i]);
}

// ---------------- K2: warp-specialized producer/consumer, fragment-reuse MMA ----------------
// 384 threads: warps 0-7 = MMA consumers (each m=64 x n=32), warps 8-11 = producers.
// smem (1024-aligned base):
#define OFF_WHI 0
#define OFF_WLO 32768
#define OFF_H(buf, part) (65536 + (buf) * 65536 + (part) * 32768)
#define OFF_SD  196608          // d[128] floats
#define OFF_SRED 197120         // sred[4][128] floats
#define K2_SMEM (199168 + 1024)

// producer: gather + relu + bf16 hi/lo split for edge-row r of `tile` into H[buf]
static __device__ __forceinline__ void k2_produce(
    int tile, long long E, int is64, const long long* p64, const int* p32,
    const float* sd, char* aHi, char* aLo, int r)
{
    long long ge = (long long)tile * TM + r;
    int s = 0, t = 0;
    if (ge < E) {
        s = is64 ? (int)p64[ge] : p32[ge];
        t = is64 ? (int)p64[E + ge] : p32[E + ge];
    }
    const float4* apb = (const float4*)(g_A + (size_t)s * HID);
    const float4* bpb = (const float4*)(g_B + (size_t)t * HID);
    const float4* dpb = (const float4*)sd;
#pragma unroll 2
    for (int half = 0; half < 2; half++) {
        const float4* ap = apb + half * 16;
        const float4* bp = bpb + half * 16;
        const float4* dp = dpb + half * 16;
#pragma unroll 4
        for (int i = 0; i < 16; i += 2) {
            float4 a0 = ap[i], a1 = ap[i + 1];
            float4 b0 = bp[i], b1 = bp[i + 1];
            float4 d0 = dp[i], d1 = dp[i + 1];
            float h[8];
            h[0] = fmaxf(a0.x + b0.x + d0.x, 0.f);
            h[1] = fmaxf(a0.y + b0.y + d0.y, 0.f);
            h[2] = fmaxf(a0.z + b0.z + d0.z, 0.f);
            h[3] = fmaxf(a0.w + b0.w + d0.w, 0.f);
            h[4] = fmaxf(a1.x + b1.x + d1.x, 0.f);
            h[5] = fmaxf(a1.y + b1.y + d1.y, 0.f);
            h[6] = fmaxf(a1.z + b1.z + d1.z, 0.f);
            h[7] = fmaxf(a1.w + b1.w + d1.w, 0.f);
            u32 uh[4], ul[4];
#pragma unroll
            for (int j = 0; j < 4; j++) {
                u32 ph = bf2(h[2 * j], h[2 * j + 1]);
                float r0 = __uint_as_float(ph << 16);
                float r1 = __uint_as_float(ph & 0xFFFF0000u);
                uh[j] = ph;
                ul[j] = bf2(h[2 * j] - r0, h[2 * j + 1] - r1);
            }
            int o = bofs(r, half * 64 + i * 4);
            *(uint4*)(aHi + o) = make_uint4(uh[0], uh[1], uh[2], uh[3]);
            *(uint4*)(aLo + o) = make_uint4(ul[0], ul[1], ul[2], ul[3]);
        }
    }
}

__global__ void __launch_bounds__(384, 1)
k2_main(const void* __restrict__ ei, const float* __restrict__ b3,
        float* __restrict__ out, int E, int ntiles) {
    extern __shared__ char dsm[];
    u32 braw = smem_u32(dsm);
    u32 base = (braw + 1023u) & ~1023u;
    char* sm = dsm + (base - braw);

    int tid  = threadIdx.x;
    int wid  = tid >> 5, lane = tid & 31;
    int is64 = g_is64;
    const long long* p64 = (const long long*)ei;
    const int*       p32 = (const int*)ei;

    float* sd   = (float*)(sm + OFF_SD);
    float* sred = (float*)(sm + OFF_SRED);

    // stage W2' bf16 hi/lo + d into smem (all 384 threads)
    {
        uint4* dh = (uint4*)(sm + OFF_WHI);
        uint4* dl = (uint4*)(sm + OFF_WLO);
        const uint4* shi = (const uint4*)g_Whi;
        const uint4* slo = (const uint4*)g_Wlo;
        for (int i = tid; i < 2048; i += 384) { dh[i] = shi[i]; dl[i] = slo[i]; }
        if (tid < HID) sd[tid] = g_d[tid];
    }
    float bias3 = b3[0];
    u32 wHiB = base + OFF_WHI, wLoB = base + OFF_WLO;

    // consumer constants: warp tile = m 64 (wm) x n 32 (wn)
    int wm = (wid >> 2) & 1, wn = wid & 3;
    int li = lane & 7, grp = lane >> 3;
    float2 wb[8];
#pragma unroll
    for (int nt = 0; nt < 4; nt++)
#pragma unroll
        for (int cp = 0; cp < 2; cp++)
            wb[nt * 2 + cp] = g_w3b2[32 * wn + nt * 8 + 2 * (lane & 3) + cp];
    int kgA = (grp >> 1) * 8;
    int kgB = (grp & 1) * 8;
    int nB0 = 32 * wn + (grp >> 1) * 8 + li;
    int nB1 = nB0 + 16;
    int bq0 = ((nB0 >> 3) << 10) + ((nB0 & 7) << 7);
    int bq1 = ((nB1 >> 3) << 10) + ((nB1 & 7) << 7);
    // A row-part per mt (4 x m16 tiles)
    int rp[4];
#pragma unroll
    for (int mt = 0; mt < 4; mt++) {
        int rA = wm * 64 + mt * 16 + (grp & 1) * 8 + li;
        rp[mt] = ((rA >> 3) << 10) + ((rA & 7) << 7);
    }

    __syncthreads();  // W, sd staged

    // prologue: producers fill buf0 with this block's first tile
    int first = blockIdx.x;
    if (wid >= 8 && first < ntiles)
        k2_produce(first, E, is64, p64, p32, sd,
                   sm + OFF_H(0, 0), sm + OFF_H(0, 1), tid - 256);

    int iter = 0;
    for (int tile = first; tile < ntiles; tile += gridDim.x, iter++) {
        int buf = iter & 1;
        __syncthreads();  // H[buf] ready; H[buf^1] free

        if (wid < 8) {
            // ============ CONSUMERS: fused 3-pass MMA, every fragment loaded once ============
            u32 hHiB = base + OFF_H(buf, 0);
            u32 hLoB = base + OFF_H(buf, 1);

            float acc[4][4][4];
#pragma unroll
            for (int mt = 0; mt < 4; mt++)
#pragma unroll
                for (int nt = 0; nt < 4; nt++)
#pragma unroll
                    for (int q = 0; q < 4; q++) acc[mt][nt][q] = 0.f;

#pragma unroll 1
            for (int ks = 0; ks < 8; ks++) {
                int k0 = ks * 16;
                int kkA = k0 + kgA;
                int kpA = ((kkA >> 6) << 14) + ((kkA & 63) << 1);
                int kkB = k0 + kgB;
                int kpB = ((kkB >> 6) << 14) + ((kkB & 63) << 1);
                int oB0 = bq0 + kpB; oB0 ^= ((oB0 >> 3) & 0x70);
                int oB1 = bq1 + kpB; oB1 ^= ((oB1 >> 3) & 0x70);

                u32 bh0[4], bh1[4], bl0[4], bl1[4];
                ldsm4(bh0, wHiB + (u32)oB0);
                ldsm4(bh1, wHiB + (u32)oB1);
                ldsm4(bl0, wLoB + (u32)oB0);
                ldsm4(bl1, wLoB + (u32)oB1);

                u32 aH[4][4], aL[4][4];
#pragma unroll
                for (int mt = 0; mt < 4; mt++) {
                    int oA = rp[mt] + kpA; oA ^= ((oA >> 3) & 0x70);
                    ldsm4(aH[mt], hHiB + (u32)oA);
                    ldsm4(aL[mt], hLoB + (u32)oA);
                }

#pragma unroll
                for (int mt = 0; mt < 4; mt++) {
                    // hi x hi
                    mma16816(acc[mt][0], aH[mt], bh0[0], bh0[1]);
                    mma16816(acc[mt][1], aH[mt], bh0[2], bh0[3]);
                    mma16816(acc[mt][2], aH[mt], bh1[0], bh1[1]);
                    mma16816(acc[mt][3], aH[mt], bh1[2], bh1[3]);
                    // hi x lo
                    mma16816(acc[mt][0], aH[mt], bl0[0], bl0[1]);
                    mma16816(acc[mt][1], aH[mt], bl0[2], bl0[3]);
                    mma16816(acc[mt][2], aH[mt], bl1[0], bl1[1]);
                    mma16816(acc[mt][3], aH[mt], bl1[2], bl1[3]);
                    // lo x hi
                    mma16816(acc[mt][0], aL[mt], bh0[0], bh0[1]);
                    mma16816(acc[mt][1], aL[mt], bh0[2], bh0[3]);
                    mma16816(acc[mt][2], aL[mt], bh1[0], bh1[1]);
                    mma16816(acc[mt][3], aL[mt], bh1[2], bh1[3]);
                }
            }

            // epilogue: relu(acc + b2') . w3, quad-reduce, stash per-warp partial
#pragma unroll
            for (int mt = 0; mt < 4; mt++) {
                float pl = 0.f, ph = 0.f;
#pragma unroll
                for (int nt = 0; nt < 4; nt++)
#pragma unroll
                    for (int cp = 0; cp < 2; cp++) {
                        float2 w = wb[nt * 2 + cp];
                        pl = fmaf(fmaxf(acc[mt][nt][cp]     + w.x, 0.f), w.y, pl);
                        ph = fmaf(fmaxf(acc[mt][nt][2 + cp] + w.x, 0.f), w.y, ph);
                    }
                pl += __shfl_xor_sync(0xffffffffu, pl, 1);
                pl += __shfl_xor_sync(0xffffffffu, pl, 2);
                ph += __shfl_xor_sync(0xffffffffu, ph, 1);
                ph += __shfl_xor_sync(0xffffffffu, ph, 2);
                if ((lane & 3) == 0) {
                    int r = wm * 64 + mt * 16 + (lane >> 2);
                    sred[wn * 128 + r]     = pl;
                    sred[wn * 128 + r + 8] = ph;
                }
            }
            // consumer-only barrier, then final cross-warp sum + store
            asm volatile("bar.sync 1, 256;" ::: "memory");
            if (tid < TM) {
                long long ge = (long long)tile * TM + tid;
                if (ge < E) {
                    float v = sred[tid] + sred[128 + tid] + sred[256 + tid] + sred[384 + tid];
                    out[ge] = v + bias3;
                }
            }
        } else {
            // ============ PRODUCERS: transform tile+grid into H[buf^1] ============
            int nt = tile + gridDim.x;
            if (nt < ntiles)
                k2_produce(nt, E, is64, p64, p32, sd,
                           sm + OFF_H(buf ^ 1, 0), sm + OFF_H(buf ^ 1, 1), tid - 256);
        }
    }
}

// ---------------- launch ----------------
extern "C" void kernel_launch(void* const* d_in, const int* in_sizes, int n_in,
                              void* d_out, int out_size) {
    const float* z     = (const float*)d_in[0];
    const void*  ei    = d_in[1];
    const float* c     = (const float*)d_in[2];
    const float* W1    = (const float*)d_in[3];
    const float* b1    = (const float*)d_in[4];
    const float* gamma = (const float*)d_in[5];
    const float* beta  = (const float*)d_in[6];
    const float* W2    = (const float*)d_in[7];
    const float* b2    = (const float*)d_in[8];
    const float* W3    = (const float*)d_in[9];
    const float* b3    = (const float*)d_in[10];
    float* out = (float*)d_out;

    int N = in_sizes[0] / ZD;
    int E = in_sizes[1] / 2;

    cudaFuncSetAttribute(k2_main, cudaFuncAttributeMaxDynamicSharedMemorySize, K2_SMEM);

    k0_nodes<<<(N + NPB - 1) / NPB + 1, 128>>>(z, W1, N, (const unsigned int*)ei, c, b1);
    k1_stats<<<K1_BLOCKS, 128>>>(ei, E);
    k15_fold<<<1, 128>>>(gamma, beta, W2, b2, W3, 1.0 / (double)E);
    int ntiles = (E + TM - 1) / TM;
    k2_main<<<K2_GRID, 384, K2_SMEM>>>(ei, b3, out, E, ntiles);
}

// round 8
// speedup vs baseline: 2.8773x; 1.2133x over previous
#include <cuda_runtime.h>
#include <cuda_bf16.h>
#include <stdint.h>

#define NODES_MAX 50000
#define HID 128
#define ZD 64
#define NPB 16          // nodes per block in K0
#define TM 128          // edges per tile in K2
#define K1_BLOCKS 1184  // 148 SMs * 8
#define K2_GRID 148

typedef unsigned long long u64;
typedef unsigned int u32;

// ---------------- static device scratch ----------------
__device__ float  g_A[NODES_MAX * HID];     // z @ W1[0:64]
__device__ float  g_B[NODES_MAX * HID];     // z @ W1[64:128]
__device__ float  g_d[HID];                 // c @ W1[128:132] + b1
__device__ double g_sum[HID];
__device__ double g_sumsq[HID];
__device__ unsigned short g_Whi[16384];     // BN-folded W2 bf16-hi, MMA swizzled layout
__device__ unsigned short g_Wlo[16384];     // bf16-lo residual
__device__ float2 g_w3b2[HID];              // (b2_folded, w3) per feature
__device__ int    g_is64;

// ---------------- helpers ----------------
__device__ __forceinline__ u32 smem_u32(const void* p) {
    u32 a;
    asm("{ .reg .u64 t; cvta.to.shared.u64 t, %1; cvt.u32.u64 %0, t; }" : "=r"(a) : "l"(p));
    return a;
}
// packed bf16x2 convert: low half <- lo, high half <- hi
__device__ __forceinline__ u32 bf2(float lo, float hi) {
    u32 r;
    asm("cvt.rn.bf16x2.f32 %0, %1, %2;" : "=r"(r) : "f"(hi), "f"(lo));
    return r;
}
__device__ __forceinline__ void ldsm4(u32* r, u32 addr) {
    asm volatile("ldmatrix.sync.aligned.m8n8.x4.shared.b16 {%0,%1,%2,%3}, [%4];"
                 : "=r"(r[0]), "=r"(r[1]), "=r"(r[2]), "=r"(r[3]) : "r"(addr));
}
__device__ __forceinline__ void mma16816(float* c, const u32* a, u32 b0, u32 b1) {
    asm volatile(
        "mma.sync.aligned.m16n8k16.row.col.f32.bf16.bf16.f32 "
        "{%0,%1,%2,%3}, {%4,%5,%6,%7}, {%8,%9}, {%0,%1,%2,%3};"
        : "+f"(c[0]), "+f"(c[1]), "+f"(c[2]), "+f"(c[3])
        : "r"(a[0]), "r"(a[1]), "r"(a[2]), "r"(a[3]), "r"(b0), "r"(b1));
}

// MMA-layout byte offset for element (row r, col k) in a 128x128 bf16 K-major
// SW128 blocked-atom tile: atom = 8 rows x 64 bf16 (1024B), 16 atom-rows x 2 atom-cols.
__device__ __forceinline__ int bofs(int r, int k) {
    int off = ((r >> 3) << 10) + ((k >> 6) << 14) + ((r & 7) << 7) + ((k & 63) << 1);
    return off ^ ((off >> 3) & 0x70);
}

// ---------------- K0: per-node partial products (+fused detect & k0b in extra block) ----------------
__global__ void k0_nodes(const float* __restrict__ z, const float* __restrict__ W1, int N,
                         const unsigned int* __restrict__ eiw,
                         const float* __restrict__ c, const float* __restrict__ b1) {
    __shared__ float zs[NPB * ZD];
    int tid = threadIdx.x;

    if (blockIdx.x == gridDim.x - 1) {
        // --- fused k_detect: is edge_index int64 or int32? ---
        __shared__ int nz;
        if (tid == 0) nz = 0;
        __syncthreads();
        if (eiw[2 * tid + 1] != 0u) atomicAdd(&nz, 1);
        __syncthreads();
        if (tid == 0) g_is64 = (nz == 0) ? 1 : 0;
        // --- fused k0b: d = c@W1c + b1, zero BN accumulators ---
        float v = b1[tid];
#pragma unroll
        for (int k = 0; k < 4; k++) v = fmaf(c[k], W1[(2 * ZD + k) * HID + tid], v);
        g_d[tid]     = v;
        g_sum[tid]   = 0.0;
        g_sumsq[tid] = 0.0;
        return;
    }

    int base = blockIdx.x * NPB;
    int nn   = N - base; if (nn > NPB) nn = NPB;

    for (int i = tid; i < nn * ZD; i += 128) zs[i] = z[base * ZD + i];
    __syncthreads();

    float a[NPB], b[NPB];
#pragma unroll
    for (int n = 0; n < NPB; n++) { a[n] = 0.f; b[n] = 0.f; }

#pragma unroll 8
    for (int k = 0; k < ZD; k++) {
        float ws = W1[k * HID + tid];
        float wd = W1[(ZD + k) * HID + tid];
#pragma unroll
        for (int n = 0; n < NPB; n++) {
            float zk = zs[n * ZD + k];
            a[n] = fmaf(zk, ws, a[n]);
            b[n] = fmaf(zk, wd, b[n]);
        }
    }
    for (int n = 0; n < nn; n++) {
        g_A[(base + n) * HID + tid] = a[n];
        g_B[(base + n) * HID + tid] = b[n];
    }
}

// ---------------- K1: BN statistics pass ----------------
template<bool IS64>
__device__ __forceinline__ int ldi(const void* ei, long long pos) {
    return IS64 ? (int)((const long long*)ei)[pos] : ((const int*)ei)[pos];
}

template<bool IS64>
__device__ __forceinline__ void k1_body(const void* __restrict__ ei, int E) {
    int j = threadIdx.x;
    float dreg = g_d[j];

    int per = (E + gridDim.x - 1) / (int)gridDim.x;
    int e0 = blockIdx.x * per;
    int e1 = e0 + per; if (e1 > E) e1 = E;

    float s1 = 0.f, s2 = 0.f;
    int e = e0;
    for (; e + 8 <= e1; e += 8) {
        int s[8], t[8];
#pragma unroll
        for (int i = 0; i < 8; i++) s[i] = ldi<IS64>(ei, e + i);
#pragma unroll
        for (int i = 0; i < 8; i++) t[i] = ldi<IS64>(ei, (long long)E + e + i);
        float av[8], bv[8];
#pragma unroll
        for (int i = 0; i < 8; i++) { av[i] = g_A[s[i] * HID + j]; bv[i] = g_B[t[i] * HID + j]; }
#pragma unroll
        for (int i = 0; i < 8; i++) {
            float h = fmaxf(av[i] + bv[i] + dreg, 0.f);
            s1 += h; s2 = fmaf(h, h, s2);
        }
    }
    for (; e < e1; e++) {
        int s = ldi<IS64>(ei, e);
        int t = ldi<IS64>(ei, (long long)E + e);
        float h = fmaxf(g_A[s * HID + j] + g_B[t * HID + j] + dreg, 0.f);
        s1 += h; s2 = fmaf(h, h, s2);
    }
    atomicAdd(&g_sum[j],   (double)s1);
    atomicAdd(&g_sumsq[j], (double)s2);
}

__global__ void k1_stats(const void* __restrict__ ei, int E) {
    if (g_is64) k1_body<true>(ei, E);
    else        k1_body<false>(ei, E);
}

// ---------------- K1.5: fold BN into W2 -> bf16 hi/lo in MMA swizzled layout ----------------
__global__ void k15_fold(const float* __restrict__ gamma, const float* __restrict__ beta,
                         const float* __restrict__ W2, const float* __restrict__ b2,
                         const float* __restrict__ W3, double invE) {
    __shared__ float gsc[HID], gsh[HID];
    int i = threadIdx.x;   // output feature f of layer 2

    double m = g_sum[i] * invE;
    double v = g_sumsq[i] * invE - m * m;
    float x = (float)v + 1e-5f;
    float s = rsqrtf(x);
    s = s * (1.5f - 0.5f * x * s * s);  // Newton refine
    float g = s * gamma[i];
    gsc[i] = g;
    gsh[i] = beta[i] - (float)m * g;
    __syncthreads();

    float bb = b2[i];
    for (int k = 0; k < HID; k++) {
        float w = W2[k * HID + i];           // W2[k][f=i]
        float wf = gsc[k] * w;               // BN scale folded (per input k)
        __nv_bfloat16 hb = __float2bfloat16(wf);
        float hf = __bfloat162float(hb);
        __nv_bfloat16 lb = __float2bfloat16(wf - hf);
        int o = bofs(i, k) >> 1;             // row = feature f, col = k
        g_Whi[o] = *(const unsigned short*)&hb;
        g_Wlo[o] = *(const unsigned short*)&lb;
        bb = fmaf(gsh[k], w, bb);
    }
    g_w3b2[i] = make_float2(bb, W3[i]);
}

// ---------------- K2: warp-specialized producer/consumer, coalesced gather ----------------
// 384 threads: warps 0-7 = MMA consumers (each m=64 x n=32), warps 8-11 = producers.
// Producers: 8 lanes cooperate per edge-row -> every LDG.128 touches 4 lines (wavefront floor).
// smem (1024-aligned base):
#define OFF_WHI 0
#define OFF_WLO 32768
#define OFF_H(buf, part) (65536 + (buf) * 65536 + (part) * 32768)
#define OFF_SD  196608          // d[128] floats
#define OFF_SRED 197120         // sred[4][128] floats
#define K2_SMEM (199168 + 1024)

// producer: coalesced gather + relu + bf16 hi/lo split for `tile` into H buffers.
// tid_p in [0,128): lg = tid_p&7 (16B chunk within 128B segment), gr = tid_p>>3 (row group).
// dq[i] = d[i*32 + lg*4 .. +3], row-invariant, preloaded.
static __device__ __forceinline__ void k2_produce(
    int tile, long long E, int is64, const long long* p64, const int* p32,
    const float4* dq, char* aHi, char* aLo, int lg, int gr)
{
#pragma unroll 1
    for (int p = 0; p < 8; p++) {
        int r = p * 16 + gr;
        long long ge = (long long)tile * TM + r;
        int s = 0, t = 0;
        if (ge < E) {
            s = is64 ? (int)p64[ge] : p32[ge];
            t = is64 ? (int)p64[E + ge] : p32[E + ge];
        }
        const float4* ap = (const float4*)(g_A + (size_t)s * HID) + lg;
        const float4* bp = (const float4*)(g_B + (size_t)t * HID) + lg;
        float4 av[4], bv[4];
#pragma unroll
        for (int i = 0; i < 4; i++) av[i] = ap[i * 8];
#pragma unroll
        for (int i = 0; i < 4; i++) bv[i] = bp[i * 8];
#pragma unroll
        for (int i = 0; i < 4; i++) {
            float4 d = dq[i];
            float h0 = fmaxf(av[i].x + bv[i].x + d.x, 0.f);
            float h1 = fmaxf(av[i].y + bv[i].y + d.y, 0.f);
            float h2 = fmaxf(av[i].z + bv[i].z + d.z, 0.f);
            float h3 = fmaxf(av[i].w + bv[i].w + d.w, 0.f);
            u32 ph0 = bf2(h0, h1), ph1 = bf2(h2, h3);
            float r00 = __uint_as_float(ph0 << 16);
            float r01 = __uint_as_float(ph0 & 0xFFFF0000u);
            float r10 = __uint_as_float(ph1 << 16);
            float r11 = __uint_as_float(ph1 & 0xFFFF0000u);
            u32 pl0 = bf2(h0 - r00, h1 - r01);
            u32 pl1 = bf2(h2 - r10, h3 - r11);
            int o = bofs(r, i * 32 + lg * 4);
            *(uint2*)(aHi + o) = make_uint2(ph0, ph1);
            *(uint2*)(aLo + o) = make_uint2(pl0, pl1);
        }
    }
}

__global__ void __launch_bounds__(384, 1)
k2_main(const void* __restrict__ ei, const float* __restrict__ b3,
        float* __restrict__ out, int E, int ntiles) {
    extern __shared__ char dsm[];
    u32 braw = smem_u32(dsm);
    u32 base = (braw + 1023u) & ~1023u;
    char* sm = dsm + (base - braw);

    int tid  = threadIdx.x;
    int wid  = tid >> 5, lane = tid & 31;
    int is64 = g_is64;
    const long long* p64 = (const long long*)ei;
    const int*       p32 = (const int*)ei;

    float* sd   = (float*)(sm + OFF_SD);
    float* sred = (float*)(sm + OFF_SRED);

    // stage W2' bf16 hi/lo + d into smem (all 384 threads)
    {
        uint4* dh = (uint4*)(sm + OFF_WHI);
        uint4* dl = (uint4*)(sm + OFF_WLO);
        const uint4* shi = (const uint4*)g_Whi;
        const uint4* slo = (const uint4*)g_Wlo;
        for (int i = tid; i < 2048; i += 384) { dh[i] = shi[i]; dl[i] = slo[i]; }
        if (tid < HID) sd[tid] = g_d[tid];
    }
    float bias3 = b3[0];
    u32 wHiB = base + OFF_WHI, wLoB = base + OFF_WLO;

    // consumer constants: warp tile = m 64 (wm) x n 32 (wn)
    int wm = (wid >> 2) & 1, wn = wid & 3;
    int li = lane & 7, grp = lane >> 3;
    float2 wb[8];
#pragma unroll
    for (int nt = 0; nt < 4; nt++)
#pragma unroll
        for (int cp = 0; cp < 2; cp++)
            wb[nt * 2 + cp] = g_w3b2[32 * wn + nt * 8 + 2 * (lane & 3) + cp];
    int kgA = (grp >> 1) * 8;
    int kgB = (grp & 1) * 8;
    int nB0 = 32 * wn + (grp >> 1) * 8 + li;
    int nB1 = nB0 + 16;
    int bq0 = ((nB0 >> 3) << 10) + ((nB0 & 7) << 7);
    int bq1 = ((nB1 >> 3) << 10) + ((nB1 & 7) << 7);
    // A row-part per mt (4 x m16 tiles)
    int rp[4];
#pragma unroll
    for (int mt = 0; mt < 4; mt++) {
        int rA = wm * 64 + mt * 16 + (grp & 1) * 8 + li;
        rp[mt] = ((rA >> 3) << 10) + ((rA & 7) << 7);
    }

    // producer constants
    int tid_p = tid - 256;
    int lg = tid_p & 7, gr = tid_p >> 3;
    float4 dq[4];
    if (wid >= 8) {
#pragma unroll
        for (int i = 0; i < 4; i++) dq[i] = ((const float4*)g_d)[i * 8 + lg];
    }

    __syncthreads();  // W, sd staged

    // prologue: producers fill buf0 with this block's first tile
    int first = blockIdx.x;
    if (wid >= 8 && first < ntiles)
        k2_produce(first, E, is64, p64, p32, dq,
                   sm + OFF_H(0, 0), sm + OFF_H(0, 1), lg, gr);

    int iter = 0;
    for (int tile = first; tile < ntiles; tile += gridDim.x, iter++) {
        int buf = iter & 1;
        __syncthreads();  // H[buf] ready; H[buf^1] free

        if (wid < 8) {
            // ============ CONSUMERS: fused 3-pass MMA, every fragment loaded once ============
            u32 hHiB = base + OFF_H(buf, 0);
            u32 hLoB = base + OFF_H(buf, 1);

            float acc[4][4][4];
#pragma unroll
            for (int mt = 0; mt < 4; mt++)
#pragma unroll
                for (int nt = 0; nt < 4; nt++)
#pragma unroll
                    for (int q = 0; q < 4; q++) acc[mt][nt][q] = 0.f;

#pragma unroll 1
            for (int ks = 0; ks < 8; ks++) {
                int k0 = ks * 16;
                int kkA = k0 + kgA;
                int kpA = ((kkA >> 6) << 14) + ((kkA & 63) << 1);
                int kkB = k0 + kgB;
                int kpB = ((kkB >> 6) << 14) + ((kkB & 63) << 1);
                int oB0 = bq0 + kpB; oB0 ^= ((oB0 >> 3) & 0x70);
                int oB1 = bq1 + kpB; oB1 ^= ((oB1 >> 3) & 0x70);

                u32 bh0[4], bh1[4], bl0[4], bl1[4];
                ldsm4(bh0, wHiB + (u32)oB0);
                ldsm4(bh1, wHiB + (u32)oB1);
                ldsm4(bl0, wLoB + (u32)oB0);
                ldsm4(bl1, wLoB + (u32)oB1);

                u32 aH[4][4], aL[4][4];
#pragma unroll
                for (int mt = 0; mt < 4; mt++) {
                    int oA = rp[mt] + kpA; oA ^= ((oA >> 3) & 0x70);
                    ldsm4(aH[mt], hHiB + (u32)oA);
                    ldsm4(aL[mt], hLoB + (u32)oA);
                }

#pragma unroll
                for (int mt = 0; mt < 4; mt++) {
                    // hi x hi
                    mma16816(acc[mt][0], aH[mt], bh0[0], bh0[1]);
                    mma16816(acc[mt][1], aH[mt], bh0[2], bh0[3]);
                    mma16816(acc[mt][2], aH[mt], bh1[0], bh1[1]);
                    mma16816(acc[mt][3], aH[mt], bh1[2], bh1[3]);
                    // hi x lo
                    mma16816(acc[mt][0], aH[mt], bl0[0], bl0[1]);
                    mma16816(acc[mt][1], aH[mt], bl0[2], bl0[3]);
                    mma16816(acc[mt][2], aH[mt], bl1[0], bl1[1]);
                    mma16816(acc[mt][3], aH[mt], bl1[2], bl1[3]);
                    // lo x hi
                    mma16816(acc[mt][0], aL[mt], bh0[0], bh0[1]);
                    mma16816(acc[mt][1], aL[mt], bh0[2], bh0[3]);
                    mma16816(acc[mt][2], aL[mt], bh1[0], bh1[1]);
                    mma16816(acc[mt][3], aL[mt], bh1[2], bh1[3]);
                }
            }

            // epilogue: relu(acc + b2') . w3, quad-reduce, stash per-warp partial
#pragma unroll
            for (int mt = 0; mt < 4; mt++) {
                float pl = 0.f, ph = 0.f;
#pragma unroll
                for (int nt = 0; nt < 4; nt++)
#pragma unroll
                    for (int cp = 0; cp < 2; cp++) {
                        float2 w = wb[nt * 2 + cp];
                        pl = fmaf(fmaxf(acc[mt][nt][cp]     + w.x, 0.f), w.y, pl);
                        ph = fmaf(fmaxf(acc[mt][nt][2 + cp] + w.x, 0.f), w.y, ph);
                    }
                pl += __shfl_xor_sync(0xffffffffu, pl, 1);
                pl += __shfl_xor_sync(0xffffffffu, pl, 2);
                ph += __shfl_xor_sync(0xffffffffu, ph, 1);
                ph += __shfl_xor_sync(0xffffffffu, ph, 2);
                if ((lane & 3) == 0) {
                    int r = wm * 64 + mt * 16 + (lane >> 2);
                    sred[wn * 128 + r]     = pl;
                    sred[wn * 128 + r + 8] = ph;
                }
            }
            // consumer-only barrier, then final cross-warp sum + store
            asm volatile("bar.sync 1, 256;" ::: "memory");
            if (tid < TM) {
                long long ge = (long long)tile * TM + tid;
                if (ge < E) {
                    float v = sred[tid] + sred[128 + tid] + sred[256 + tid] + sred[384 + tid];
                    out[ge] = v + bias3;
                }
            }
        } else {
            // ============ PRODUCERS: transform tile+grid into H[buf^1] ============
            int nt = tile + gridDim.x;
            if (nt < ntiles)
                k2_produce(nt, E, is64, p64, p32, dq,
                           sm + OFF_H(buf ^ 1, 0), sm + OFF_H(buf ^ 1, 1), lg, gr);
        }
    }
}

// ---------------- launch ----------------
extern "C" void kernel_launch(void* const* d_in, const int* in_sizes, int n_in,
                              void* d_out, int out_size) {
    const float* z     = (const float*)d_in[0];
    const void*  ei    = d_in[1];
    const float* c     = (const float*)d_in[2];
    const float* W1    = (const float*)d_in[3];
    const float* b1    = (const float*)d_in[4];
    const float* gamma = (const float*)d_in[5];
    const float* beta  = (const float*)d_in[6];
    const float* W2    = (const float*)d_in[7];
    const float* b2    = (const float*)d_in[8];
    const float* W3    = (const float*)d_in[9];
    const float* b3    = (const float*)d_in[10];
    float* out = (float*)d_out;

    int N = in_sizes[0] / ZD;
    int E = in_sizes[1] / 2;

    cudaFuncSetAttribute(k2_main, cudaFuncAttributeMaxDynamicSharedMemorySize, K2_SMEM);

    k0_nodes<<<(N + NPB - 1) / NPB + 1, 128>>>(z, W1, N, (const unsigned int*)ei, c, b1);
    k1_stats<<<K1_BLOCKS, 128>>>(ei, E);
    k15_fold<<<1, 128>>>(gamma, beta, W2, b2, W3, 1.0 / (double)E);
    int ntiles = (E + TM - 1) / TM;
    k2_main<<<K2_GRID, 384, K2_SMEM>>>(ei, b3, out, E, ntiles);
}

// round 9
// speedup vs baseline: 2.8802x; 1.0010x over previous
#include <cuda_runtime.h>
#include <cuda_bf16.h>
#include <stdint.h>

#define NODES_MAX 50000
#define HID 128
#define ZD 64
#define NPB 16          // nodes per block in K0
#define TM 128          // edges per tile in K2
#define K1_BLOCKS 1184  // 148 SMs * 8
#define K2_GRID 148

typedef unsigned long long u64;
typedef unsigned int u32;

// ---------------- static device scratch ----------------
__device__ float  g_A[NODES_MAX * HID];     // z @ W1[0:64]
__device__ float  g_B[NODES_MAX * HID];     // z @ W1[64:128]
__device__ float  g_d[HID];                 // c @ W1[128:132] + b1
__device__ double g_sum[HID];
__device__ double g_sumsq[HID];
__device__ unsigned short g_Whi[16384];     // BN-folded W2 bf16-hi, MMA swizzled layout
__device__ unsigned short g_Wlo[16384];     // bf16-lo residual
__device__ float2 g_w3b2[HID];              // (b2_folded, w3) per feature
__device__ int    g_is64;

// ---------------- helpers ----------------
__device__ __forceinline__ u32 smem_u32(const void* p) {
    u32 a;
    asm("{ .reg .u64 t; cvta.to.shared.u64 t, %1; cvt.u32.u64 %0, t; }" : "=r"(a) : "l"(p));
    return a;
}
// packed bf16x2 convert: low half <- lo, high half <- hi
__device__ __forceinline__ u32 bf2(float lo, float hi) {
    u32 r;
    asm("cvt.rn.bf16x2.f32 %0, %1, %2;" : "=r"(r) : "f"(hi), "f"(lo));
    return r;
}
__device__ __forceinline__ void ldsm4(u32* r, u32 addr) {
    asm volatile("ldmatrix.sync.aligned.m8n8.x4.shared.b16 {%0,%1,%2,%3}, [%4];"
                 : "=r"(r[0]), "=r"(r[1]), "=r"(r[2]), "=r"(r[3]) : "r"(addr));
}
__device__ __forceinline__ void mma16816(float* c, const u32* a, u32 b0, u32 b1) {
    asm volatile(
        "mma.sync.aligned.m16n8k16.row.col.f32.bf16.bf16.f32 "
        "{%0,%1,%2,%3}, {%4,%5,%6,%7}, {%8,%9}, {%0,%1,%2,%3};"
        : "+f"(c[0]), "+f"(c[1]), "+f"(c[2]), "+f"(c[3])
        : "r"(a[0]), "r"(a[1]), "r"(a[2]), "r"(a[3]), "r"(b0), "r"(b1));
}

// MMA-layout byte offset for element (row r, col k) in a 128x128 bf16 K-major
// SW128 blocked-atom tile: atom = 8 rows x 64 bf16 (1024B), 16 atom-rows x 2 atom-cols.
__device__ __forceinline__ int bofs(int r, int k) {
    int off = ((r >> 3) << 10) + ((k >> 6) << 14) + ((r & 7) << 7) + ((k & 63) << 1);
    return off ^ ((off >> 3) & 0x70);
}

// ---------------- K0: per-node partial products (+fused detect & k0b in extra block) ----------------
__global__ void k0_nodes(const float* __restrict__ z, const float* __restrict__ W1, int N,
                         const unsigned int* __restrict__ eiw,
                         const float* __restrict__ c, const float* __restrict__ b1) {
    __shared__ float zs[NPB * ZD];
    int tid = threadIdx.x;

    if (blockIdx.x == gridDim.x - 1) {
        // --- fused k_detect: is edge_index int64 or int32? ---
        __shared__ int nz;
        if (tid == 0) nz = 0;
        __syncthreads();
        if (eiw[2 * tid + 1] != 0u) atomicAdd(&nz, 1);
        __syncthreads();
        if (tid == 0) g_is64 = (nz == 0) ? 1 : 0;
        // --- fused k0b: d = c@W1c + b1, zero BN accumulators ---
        float v = b1[tid];
#pragma unroll
        for (int k = 0; k < 4; k++) v = fmaf(c[k], W1[(2 * ZD + k) * HID + tid], v);
        g_d[tid]     = v;
        g_sum[tid]   = 0.0;
        g_sumsq[tid] = 0.0;
        return;
    }

    int base = blockIdx.x * NPB;
    int nn   = N - base; if (nn > NPB) nn = NPB;

    for (int i = tid; i < nn * ZD; i += 128) zs[i] = z[base * ZD + i];
    __syncthreads();

    float a[NPB], b[NPB];
#pragma unroll
    for (int n = 0; n < NPB; n++) { a[n] = 0.f; b[n] = 0.f; }

#pragma unroll 8
    for (int k = 0; k < ZD; k++) {
        float ws = W1[k * HID + tid];
        float wd = W1[(ZD + k) * HID + tid];
#pragma unroll
        for (int n = 0; n < NPB; n++) {
            float zk = zs[n * ZD + k];
            a[n] = fmaf(zk, ws, a[n]);
            b[n] = fmaf(zk, wd, b[n]);
        }
    }
    for (int n = 0; n < nn; n++) {
        g_A[(base + n) * HID + tid] = a[n];
        g_B[(base + n) * HID + tid] = b[n];
    }
}

// ---------------- K1: BN statistics pass ----------------
template<bool IS64>
__device__ __forceinline__ int ldi(const void* ei, long long pos) {
    return IS64 ? (int)((const long long*)ei)[pos] : ((const int*)ei)[pos];
}

template<bool IS64>
__device__ __forceinline__ void k1_body(const void* __restrict__ ei, int E) {
    int j = threadIdx.x;
    float dreg = g_d[j];

    int per = (E + gridDim.x - 1) / (int)gridDim.x;
    int e0 = blockIdx.x * per;
    int e1 = e0 + per; if (e1 > E) e1 = E;

    float s1 = 0.f, s2 = 0.f;
    int e = e0;
    for (; e + 8 <= e1; e += 8) {
        int s[8], t[8];
#pragma unroll
        for (int i = 0; i < 8; i++) s[i] = ldi<IS64>(ei, e + i);
#pragma unroll
        for (int i = 0; i < 8; i++) t[i] = ldi<IS64>(ei, (long long)E + e + i);
        float av[8], bv[8];
#pragma unroll
        for (int i = 0; i < 8; i++) { av[i] = g_A[s[i] * HID + j]; bv[i] = g_B[t[i] * HID + j]; }
#pragma unroll
        for (int i = 0; i < 8; i++) {
            float h = fmaxf(av[i] + bv[i] + dreg, 0.f);
            s1 += h; s2 = fmaf(h, h, s2);
        }
    }
    for (; e < e1; e++) {
        int s = ldi<IS64>(ei, e);
        int t = ldi<IS64>(ei, (long long)E + e);
        float h = fmaxf(g_A[s * HID + j] + g_B[t * HID + j] + dreg, 0.f);
        s1 += h; s2 = fmaf(h, h, s2);
    }
    atomicAdd(&g_sum[j],   (double)s1);
    atomicAdd(&g_sumsq[j], (double)s2);
}

__global__ void k1_stats(const void* __restrict__ ei, int E) {
    if (g_is64) k1_body<true>(ei, E);
    else        k1_body<false>(ei, E);
}

// ---------------- K1.5: fold BN into W2 -> bf16 hi/lo in MMA swizzled layout ----------------
__global__ void k15_fold(const float* __restrict__ gamma, const float* __restrict__ beta,
                         const float* __restrict__ W2, const float* __restrict__ b2,
                         const float* __restrict__ W3, double invE) {
    __shared__ float gsc[HID], gsh[HID];
    int i = threadIdx.x;   // output feature f of layer 2

    double m = g_sum[i] * invE;
    double v = g_sumsq[i] * invE - m * m;
    float x = (float)v + 1e-5f;
    float s = rsqrtf(x);
    s = s * (1.5f - 0.5f * x * s * s);  // Newton refine
    float g = s * gamma[i];
    gsc[i] = g;
    gsh[i] = beta[i] - (float)m * g;
    __syncthreads();

    float bb = b2[i];
    for (int k = 0; k < HID; k++) {
        float w = W2[k * HID + i];           // W2[k][f=i]
        float wf = gsc[k] * w;               // BN scale folded (per input k)
        __nv_bfloat16 hb = __float2bfloat16(wf);
        float hf = __bfloat162float(hb);
        __nv_bfloat16 lb = __float2bfloat16(wf - hf);
        int o = bofs(i, k) >> 1;             // row = feature f, col = k
        g_Whi[o] = *(const unsigned short*)&hb;
        g_Wlo[o] = *(const unsigned short*)&lb;
        bb = fmaf(gsh[k], w, bb);
    }
    g_w3b2[i] = make_float2(bb, W3[i]);
}

// ---------------- K2: warp-specialized producer/consumer, 16 MMA warps ----------------
// 640 threads: warps 0-15 = MMA consumers (each m=32 x n=32), warps 16-19 = producers.
// smem (1024-aligned base):
#define OFF_WHI 0
#define OFF_WLO 32768
#define OFF_H(buf, part) (65536 + (buf) * 65536 + (part) * 32768)
#define OFF_SWB 196608          // w3b2 float2[128] (1KB)
#define OFF_SRED 197632         // sred[4][128] floats
#define K2_SMEM (199680 + 1024)

// producer: coalesced gather + relu + bf16 hi/lo split for `tile` into H buffers.
// tid_p in [0,128): lg = tid_p&7 (16B chunk within 128B segment), gr = tid_p>>3 (row group).
static __device__ __forceinline__ void k2_produce(
    int tile, long long E, int is64, const long long* p64, const int* p32,
    const float4* dq, char* aHi, char* aLo, int lg, int gr)
{
#pragma unroll 1
    for (int p = 0; p < 8; p++) {
        int r = p * 16 + gr;
        long long ge = (long long)tile * TM + r;
        int s = 0, t = 0;
        if (ge < E) {
            s = is64 ? (int)p64[ge] : p32[ge];
            t = is64 ? (int)p64[E + ge] : p32[E + ge];
        }
        const float4* ap = (const float4*)(g_A + (size_t)s * HID) + lg;
        const float4* bp = (const float4*)(g_B + (size_t)t * HID) + lg;
        float4 av[4], bv[4];
#pragma unroll
        for (int i = 0; i < 4; i++) av[i] = ap[i * 8];
#pragma unroll
        for (int i = 0; i < 4; i++) bv[i] = bp[i * 8];
#pragma unroll
        for (int i = 0; i < 4; i++) {
            float4 d = dq[i];
            float h0 = fmaxf(av[i].x + bv[i].x + d.x, 0.f);
            float h1 = fmaxf(av[i].y + bv[i].y + d.y, 0.f);
            float h2 = fmaxf(av[i].z + bv[i].z + d.z, 0.f);
            float h3 = fmaxf(av[i].w + bv[i].w + d.w, 0.f);
            u32 ph0 = bf2(h0, h1), ph1 = bf2(h2, h3);
            float r00 = __uint_as_float(ph0 << 16);
            float r01 = __uint_as_float(ph0 & 0xFFFF0000u);
            float r10 = __uint_as_float(ph1 << 16);
            float r11 = __uint_as_float(ph1 & 0xFFFF0000u);
            u32 pl0 = bf2(h0 - r00, h1 - r01);
            u32 pl1 = bf2(h2 - r10, h3 - r11);
            int o = bofs(r, i * 32 + lg * 4);
            *(uint2*)(aHi + o) = make_uint2(ph0, ph1);
            *(uint2*)(aLo + o) = make_uint2(pl0, pl1);
        }
    }
}

__global__ void __launch_bounds__(640, 1)
k2_main(const void* __restrict__ ei, const float* __restrict__ b3,
        float* __restrict__ out, int E, int ntiles) {
    extern __shared__ char dsm[];
    u32 braw = smem_u32(dsm);
    u32 base = (braw + 1023u) & ~1023u;
    char* sm = dsm + (base - braw);

    int tid  = threadIdx.x;
    int wid  = tid >> 5, lane = tid & 31;
    int is64 = g_is64;
    const long long* p64 = (const long long*)ei;
    const int*       p32 = (const int*)ei;

    const float2* swb = (const float2*)(sm + OFF_SWB);
    float* sred = (float*)(sm + OFF_SRED);

    // stage W2' bf16 hi/lo + w3b2 into smem (all 640 threads)
    {
        uint4* dh = (uint4*)(sm + OFF_WHI);
        uint4* dl = (uint4*)(sm + OFF_WLO);
        const uint4* shi = (const uint4*)g_Whi;
        const uint4* slo = (const uint4*)g_Wlo;
        for (int i = tid; i < 2048; i += 640) { dh[i] = shi[i]; dl[i] = slo[i]; }
        if (tid < HID) ((float2*)(sm + OFF_SWB))[tid] = g_w3b2[tid];
    }
    float bias3 = b3[0];
    u32 wHiB = base + OFF_WHI, wLoB = base + OFF_WLO;

    // consumer constants: warp tile = m 32 (wm 0..3) x n 32 (wn 0..3)
    int wm = (wid >> 2) & 3, wn = wid & 3;
    int li = lane & 7, grp = lane >> 3;
    int kgA = (grp >> 1) * 8;
    int kgB = (grp & 1) * 8;
    int nB0 = 32 * wn + (grp >> 1) * 8 + li;
    int nB1 = nB0 + 16;
    int bq0 = ((nB0 >> 3) << 10) + ((nB0 & 7) << 7);
    int bq1 = ((nB1 >> 3) << 10) + ((nB1 & 7) << 7);
    // A row-part per mt (2 x m16 tiles)
    int rp[2];
#pragma unroll
    for (int mt = 0; mt < 2; mt++) {
        int rA = wm * 32 + mt * 16 + (grp & 1) * 8 + li;
        rp[mt] = ((rA >> 3) << 10) + ((rA & 7) << 7);
    }

    // producer constants
    int tid_p = tid - 512;
    int lg = tid_p & 7, gr = tid_p >> 3;
    float4 dq[4];
    if (wid >= 16) {
#pragma unroll
        for (int i = 0; i < 4; i++) dq[i] = ((const float4*)g_d)[i * 8 + lg];
    }

    __syncthreads();  // W, swb staged

    // prologue: producers fill buf0 with this block's first tile
    int first = blockIdx.x;
    if (wid >= 16 && first < ntiles)
        k2_produce(first, E, is64, p64, p32, dq,
                   sm + OFF_H(0, 0), sm + OFF_H(0, 1), lg, gr);

    int iter = 0;
    for (int tile = first; tile < ntiles; tile += gridDim.x, iter++) {
        int buf = iter & 1;
        __syncthreads();  // H[buf] ready; H[buf^1] free

        if (wid < 16) {
            // ============ CONSUMERS: fused 3-pass MMA, m32 x n32 per warp ============
            u32 hHiB = base + OFF_H(buf, 0);
            u32 hLoB = base + OFF_H(buf, 1);

            float acc[2][4][4];
#pragma unroll
            for (int mt = 0; mt < 2; mt++)
#pragma unroll
                for (int nt = 0; nt < 4; nt++)
#pragma unroll
                    for (int q = 0; q < 4; q++) acc[mt][nt][q] = 0.f;

#pragma unroll 1
            for (int ks = 0; ks < 8; ks++) {
                int k0 = ks * 16;
                int kkA = k0 + kgA;
                int kpA = ((kkA >> 6) << 14) + ((kkA & 63) << 1);
                int kkB = k0 + kgB;
                int kpB = ((kkB >> 6) << 14) + ((kkB & 63) << 1);
                int oB0 = bq0 + kpB; oB0 ^= ((oB0 >> 3) & 0x70);
                int oB1 = bq1 + kpB; oB1 ^= ((oB1 >> 3) & 0x70);

                u32 bh0[4], bh1[4], bl0[4], bl1[4];
                ldsm4(bh0, wHiB + (u32)oB0);
                ldsm4(bh1, wHiB + (u32)oB1);
                ldsm4(bl0, wLoB + (u32)oB0);
                ldsm4(bl1, wLoB + (u32)oB1);

#pragma unroll
                for (int mt = 0; mt < 2; mt++) {
                    int oA = rp[mt] + kpA; oA ^= ((oA >> 3) & 0x70);
                    u32 aH[4], aL[4];
                    ldsm4(aH, hHiB + (u32)oA);
                    ldsm4(aL, hLoB + (u32)oA);
                    // hi x hi
                    mma16816(acc[mt][0], aH, bh0[0], bh0[1]);
                    mma16816(acc[mt][1], aH, bh0[2], bh0[3]);
                    mma16816(acc[mt][2], aH, bh1[0], bh1[1]);
                    mma16816(acc[mt][3], aH, bh1[2], bh1[3]);
                    // hi x lo
                    mma16816(acc[mt][0], aH, bl0[0], bl0[1]);
                    mma16816(acc[mt][1], aH, bl0[2], bl0[3]);
                    mma16816(acc[mt][2], aH, bl1[0], bl1[1]);
                    mma16816(acc[mt][3], aH, bl1[2], bl1[3]);
                    // lo x hi
                    mma16816(acc[mt][0], aL, bh0[0], bh0[1]);
                    mma16816(acc[mt][1], aL, bh0[2], bh0[3]);
                    mma16816(acc[mt][2], aL, bh1[0], bh1[1]);
                    mma16816(acc[mt][3], aL, bh1[2], bh1[3]);
                }
            }

            // epilogue: relu(acc + b2') . w3, quad-reduce, stash per-warp partial
#pragma unroll
            for (int mt = 0; mt < 2; mt++) {
                float pl = 0.f, ph = 0.f;
#pragma unroll
                for (int nt = 0; nt < 4; nt++)
#pragma unroll
                    for (int cp = 0; cp < 2; cp++) {
                        float2 w = swb[32 * wn + nt * 8 + 2 * (lane & 3) + cp];
                        pl = fmaf(fmaxf(acc[mt][nt][cp]     + w.x, 0.f), w.y, pl);
                        ph = fmaf(fmaxf(acc[mt][nt][2 + cp] + w.x, 0.f), w.y, ph);
                    }
                pl += __shfl_xor_sync(0xffffffffu, pl, 1);
                pl += __shfl_xor_sync(0xffffffffu, pl, 2);
                ph += __shfl_xor_sync(0xffffffffu, ph, 1);
                ph += __shfl_xor_sync(0xffffffffu, ph, 2);
                if ((lane & 3) == 0) {
                    int r = wm * 32 + mt * 16 + (lane >> 2);
                    sred[wn * 128 + r]     = pl;
                    sred[wn * 128 + r + 8] = ph;
                }
            }
            // consumer-only barrier, then final cross-warp sum + store
            asm volatile("bar.sync 1, 512;" ::: "memory");
            if (tid < TM) {
                long long ge = (long long)tile * TM + tid;
                if (ge < E) {
                    float v = sred[tid] + sred[128 + tid] + sred[256 + tid] + sred[384 + tid];
                    out[ge] = v + bias3;
                }
            }
        } else {
            // ============ PRODUCERS: transform tile+grid into H[buf^1] ============
            int nt = tile + gridDim.x;
            if (nt < ntiles)
                k2_produce(nt, E, is64, p64, p32, dq,
                           sm + OFF_H(buf ^ 1, 0), sm + OFF_H(buf ^ 1, 1), lg, gr);
        }
    }
}

// ---------------- launch ----------------
extern "C" void kernel_launch(void* const* d_in, const int* in_sizes, int n_in,
                              void* d_out, int out_size) {
    const float* z     = (const float*)d_in[0];
    const void*  ei    = d_in[1];
    const float* c     = (const float*)d_in[2];
    const float* W1    = (const float*)d_in[3];
    const float* b1    = (const float*)d_in[4];
    const float* gamma = (const float*)d_in[5];
    const float* beta  = (const float*)d_in[6];
    const float* W2    = (const float*)d_in[7];
    const float* b2    = (const float*)d_in[8];
    const float* W3    = (const float*)d_in[9];
    const float* b3    = (const float*)d_in[10];
    float* out = (float*)d_out;

    int N = in_sizes[0] / ZD;
    int E = in_sizes[1] / 2;

    cudaFuncSetAttribute(k2_main, cudaFuncAttributeMaxDynamicSharedMemorySize, K2_SMEM);

    k0_nodes<<<(N + NPB - 1) / NPB + 1, 128>>>(z, W1, N, (const unsigned int*)ei, c, b1);
    k1_stats<<<K1_BLOCKS, 128>>>(ei, E);
    k15_fold<<<1, 128>>>(gamma, beta, W2, b2, W3, 1.0 / (double)E);
    int ntiles = (E + TM - 1) / TM;
    k2_main<<<K2_GRID, 640, K2_SMEM>>>(ei, b3, out, E, ntiles);
}

// round 10
// speedup vs baseline: 3.1748x; 1.1023x over previous
#include <cuda_runtime.h>
#include <cuda_bf16.h>
#include <stdint.h>

#define NODES_MAX 50000
#define HID 128
#define ZD 64
#define NPB 16          // nodes per block in K0
#define TM 128          // edges per tile in K2
#define K1_BLOCKS 1184  // 148 SMs * 8
#define K2_GRID 148

typedef unsigned long long u64;
typedef unsigned int u32;

// ---------------- static device scratch ----------------
__device__ float  g_A[NODES_MAX * HID];     // z @ W1[0:64]
__device__ float  g_B[NODES_MAX * HID];     // z @ W1[64:128]
__device__ float  g_d[HID];                 // c @ W1[128:132] + b1
__device__ double g_sum[HID];
__device__ double g_sumsq[HID];
__device__ unsigned short g_Whi[16384];     // BN-folded W2 bf16-hi, MMA swizzled layout
__device__ unsigned short g_Wlo[16384];     // bf16-lo residual
__device__ float2 g_w3b2[HID];              // (b2_folded, w3) per feature
__device__ int    g_is64;

// ---------------- helpers ----------------
__device__ __forceinline__ u32 smem_u32(const void* p) {
    u32 a;
    asm("{ .reg .u64 t; cvta.to.shared.u64 t, %1; cvt.u32.u64 %0, t; }" : "=r"(a) : "l"(p));
    return a;
}
// packed bf16x2 convert: low half <- lo, high half <- hi
__device__ __forceinline__ u32 bf2(float lo, float hi) {
    u32 r;
    asm("cvt.rn.bf16x2.f32 %0, %1, %2;" : "=r"(r) : "f"(hi), "f"(lo));
    return r;
}
__device__ __forceinline__ void ldsm4(u32* r, u32 addr) {
    asm volatile("ldmatrix.sync.aligned.m8n8.x4.shared.b16 {%0,%1,%2,%3}, [%4];"
                 : "=r"(r[0]), "=r"(r[1]), "=r"(r[2]), "=r"(r[3]) : "r"(addr));
}
__device__ __forceinline__ void mma16816(float* c, const u32* a, u32 b0, u32 b1) {
    asm volatile(
        "mma.sync.aligned.m16n8k16.row.col.f32.bf16.bf16.f32 "
        "{%0,%1,%2,%3}, {%4,%5,%6,%7}, {%8,%9}, {%0,%1,%2,%3};"
        : "+f"(c[0]), "+f"(c[1]), "+f"(c[2]), "+f"(c[3])
        : "r"(a[0]), "r"(a[1]), "r"(a[2]), "r"(a[3]), "r"(b0), "r"(b1));
}

// MMA-layout byte offset for element (row r, col k) in a 128x128 bf16 K-major
// SW128 blocked-atom tile: atom = 8 rows x 64 bf16 (1024B), 16 atom-rows x 2 atom-cols.
__device__ __forceinline__ int bofs(int r, int k) {
    int off = ((r >> 3) << 10) + ((k >> 6) << 14) + ((r & 7) << 7) + ((k & 63) << 1);
    return off ^ ((off >> 3) & 0x70);
}

// ---------------- K0: per-node partial products (+fused detect & k0b in extra block) ----------------
__global__ void k0_nodes(const float* __restrict__ z, const float* __restrict__ W1, int N,
                         const unsigned int* __restrict__ eiw,
                         const float* __restrict__ c, const float* __restrict__ b1) {
    __shared__ float zs[NPB * ZD];
    int tid = threadIdx.x;

    if (blockIdx.x == gridDim.x - 1) {
        // --- fused k_detect: is edge_index int64 or int32? ---
        __shared__ int nz;
        if (tid == 0) nz = 0;
        __syncthreads();
        if (eiw[2 * tid + 1] != 0u) atomicAdd(&nz, 1);
        __syncthreads();
        if (tid == 0) g_is64 = (nz == 0) ? 1 : 0;
        // --- fused k0b: d = c@W1c + b1, zero BN accumulators ---
        float v = b1[tid];
#pragma unroll
        for (int k = 0; k < 4; k++) v = fmaf(c[k], W1[(2 * ZD + k) * HID + tid], v);
        g_d[tid]     = v;
        g_sum[tid]   = 0.0;
        g_sumsq[tid] = 0.0;
        return;
    }

    int base = blockIdx.x * NPB;
    int nn   = N - base; if (nn > NPB) nn = NPB;

    for (int i = tid; i < nn * ZD; i += 128) zs[i] = z[base * ZD + i];
    __syncthreads();

    float a[NPB], b[NPB];
#pragma unroll
    for (int n = 0; n < NPB; n++) { a[n] = 0.f; b[n] = 0.f; }

#pragma unroll 8
    for (int k = 0; k < ZD; k++) {
        float ws = W1[k * HID + tid];
        float wd = W1[(ZD + k) * HID + tid];
#pragma unroll
        for (int n = 0; n < NPB; n++) {
            float zk = zs[n * ZD + k];
            a[n] = fmaf(zk, ws, a[n]);
            b[n] = fmaf(zk, wd, b[n]);
        }
    }
    for (int n = 0; n < nn; n++) {
        g_A[(base + n) * HID + tid] = a[n];
        g_B[(base + n) * HID + tid] = b[n];
    }
}

// ---------------- K1: BN statistics pass ----------------
template<bool IS64>
__device__ __forceinline__ int ldi(const void* ei, long long pos) {
    return IS64 ? (int)((const long long*)ei)[pos] : ((const int*)ei)[pos];
}

template<bool IS64>
__device__ __forceinline__ void k1_body(const void* __restrict__ ei, int E) {
    int j = threadIdx.x;
    float dreg = g_d[j];

    int per = (E + gridDim.x - 1) / (int)gridDim.x;
    int e0 = blockIdx.x * per;
    int e1 = e0 + per; if (e1 > E) e1 = E;

    float s1 = 0.f, s2 = 0.f;
    int e = e0;
    for (; e + 8 <= e1; e += 8) {
        int s[8], t[8];
#pragma unroll
        for (int i = 0; i < 8; i++) s[i] = ldi<IS64>(ei, e + i);
#pragma unroll
        for (int i = 0; i < 8; i++) t[i] = ldi<IS64>(ei, (long long)E + e + i);
        float av[8], bv[8];
#pragma unroll
        for (int i = 0; i < 8; i++) { av[i] = g_A[s[i] * HID + j]; bv[i] = g_B[t[i] * HID + j]; }
#pragma unroll
        for (int i = 0; i < 8; i++) {
            float h = fmaxf(av[i] + bv[i] + dreg, 0.f);
            s1 += h; s2 = fmaf(h, h, s2);
        }
    }
    for (; e < e1; e++) {
        int s = ldi<IS64>(ei, e);
        int t = ldi<IS64>(ei, (long long)E + e);
        float h = fmaxf(g_A[s * HID + j] + g_B[t * HID + j] + dreg, 0.f);
        s1 += h; s2 = fmaf(h, h, s2);
    }
    atomicAdd(&g_sum[j],   (double)s1);
    atomicAdd(&g_sumsq[j], (double)s2);
}

__global__ void k1_stats(const void* __restrict__ ei, int E) {
    if (g_is64) k1_body<true>(ei, E);
    else        k1_body<false>(ei, E);
}

// ---------------- K1.5: fold BN into W2 -> bf16 hi/lo in MMA swizzled layout ----------------
__global__ void k15_fold(const float* __restrict__ gamma, const float* __restrict__ beta,
                         const float* __restrict__ W2, const float* __restrict__ b2,
                         const float* __restrict__ W3, double invE) {
    __shared__ float gsc[HID], gsh[HID];
    int i = threadIdx.x;   // output feature f of layer 2

    double m = g_sum[i] * invE;
    double v = g_sumsq[i] * invE - m * m;
    float x = (float)v + 1e-5f;
    float s = rsqrtf(x);
    s = s * (1.5f - 0.5f * x * s * s);  // Newton refine
    float g = s * gamma[i];
    gsc[i] = g;
    gsh[i] = beta[i] - (float)m * g;
    __syncthreads();

    float bb = b2[i];
    for (int k = 0; k < HID; k++) {
        float w = W2[k * HID + i];           // W2[k][f=i]
        float wf = gsc[k] * w;               // BN scale folded (per input k)
        __nv_bfloat16 hb = __float2bfloat16(wf);
        float hf = __bfloat162float(hb);
        __nv_bfloat16 lb = __float2bfloat16(wf - hf);
        int o = bofs(i, k) >> 1;             // row = feature f, col = k
        g_Whi[o] = *(const unsigned short*)&hb;
        g_Wlo[o] = *(const unsigned short*)&lb;
        bb = fmaf(gsh[k], w, bb);
    }
    g_w3b2[i] = make_float2(bb, W3[i]);
}

// ---------------- K2: warp-specialized producer/consumer, 16 MMA warps ----------------
// 640 threads: warps 0-15 = MMA consumers (each m=32 x n=32), warps 16-19 = producers.
// smem (1024-aligned base):
#define OFF_WHI 0
#define OFF_WLO 32768
#define OFF_H(buf, part) (65536 + (buf) * 65536 + (part) * 32768)
#define OFF_SWB 196608          // w3b2 float2[128] (1KB)
#define OFF_SRED 197632         // sred[4][128] floats
#define K2_SMEM (199680 + 1024)

// producer: coalesced gather + relu + bf16 hi/lo split, SOFTWARE-PIPELINED.
// tid_p in [0,128): lg = tid_p&7 (16B chunk within 128B segment), gr = tid_p>>3 (row group).
// Phase 1: prefetch all 16 edge indices (independent LDGs, one latency).
// Phase 2: depth-2 row pipeline — row p+1's 8 data LDGs issued before row p converts.
static __device__ __forceinline__ void k2_produce(
    int tile, long long E, int is64, const long long* p64, const int* p32,
    const float4* dq, char* aHi, char* aLo, int lg, int gr)
{
    int sa[8], ta[8];
#pragma unroll
    for (int p = 0; p < 8; p++) {
        long long ge = (long long)tile * TM + p * 16 + gr;
        long long g2 = (ge < E) ? ge : (long long)0;
        sa[p] = is64 ? (int)p64[g2] : p32[g2];
        ta[p] = is64 ? (int)p64[E + g2] : p32[E + g2];
    }

    float4 av[2][4], bv[2][4];
    {
        const float4* ap = (const float4*)(g_A + (size_t)sa[0] * HID) + lg;
        const float4* bp = (const float4*)(g_B + (size_t)ta[0] * HID) + lg;
#pragma unroll
        for (int i = 0; i < 4; i++) av[0][i] = ap[i * 8];
#pragma unroll
        for (int i = 0; i < 4; i++) bv[0][i] = bp[i * 8];
    }

#pragma unroll
    for (int p = 0; p < 8; p++) {
        int cur = p & 1;
        if (p < 7) {
            const float4* ap = (const float4*)(g_A + (size_t)sa[p + 1] * HID) + lg;
            const float4* bp = (const float4*)(g_B + (size_t)ta[p + 1] * HID) + lg;
#pragma unroll
            for (int i = 0; i < 4; i++) av[cur ^ 1][i] = ap[i * 8];
#pragma unroll
            for (int i = 0; i < 4; i++) bv[cur ^ 1][i] = bp[i * 8];
        }
        int r = p * 16 + gr;
#pragma unroll
        for (int i = 0; i < 4; i++) {
            float4 d = dq[i];
            float4 a = av[cur][i], b = bv[cur][i];
            float h0 = fmaxf(a.x + b.x + d.x, 0.f);
            float h1 = fmaxf(a.y + b.y + d.y, 0.f);
            float h2 = fmaxf(a.z + b.z + d.z, 0.f);
            float h3 = fmaxf(a.w + b.w + d.w, 0.f);
            u32 ph0 = bf2(h0, h1), ph1 = bf2(h2, h3);
            float r00 = __uint_as_float(ph0 << 16);
            float r01 = __uint_as_float(ph0 & 0xFFFF0000u);
            float r10 = __uint_as_float(ph1 << 16);
            float r11 = __uint_as_float(ph1 & 0xFFFF0000u);
            u32 pl0 = bf2(h0 - r00, h1 - r01);
            u32 pl1 = bf2(h2 - r10, h3 - r11);
            int o = bofs(r, i * 32 + lg * 4);
            *(uint2*)(aHi + o) = make_uint2(ph0, ph1);
            *(uint2*)(aLo + o) = make_uint2(pl0, pl1);
        }
    }
}

__global__ void __launch_bounds__(640, 1)
k2_main(const void* __restrict__ ei, const float* __restrict__ b3,
        float* __restrict__ out, int E, int ntiles) {
    extern __shared__ char dsm[];
    u32 braw = smem_u32(dsm);
    u32 base = (braw + 1023u) & ~1023u;
    char* sm = dsm + (base - braw);

    int tid  = threadIdx.x;
    int wid  = tid >> 5, lane = tid & 31;
    int is64 = g_is64;
    const long long* p64 = (const long long*)ei;
    const int*       p32 = (const int*)ei;

    const float2* swb = (const float2*)(sm + OFF_SWB);
    float* sred = (float*)(sm + OFF_SRED);

    // stage W2' bf16 hi/lo + w3b2 into smem (all 640 threads)
    {
        uint4* dh = (uint4*)(sm + OFF_WHI);
        uint4* dl = (uint4*)(sm + OFF_WLO);
        const uint4* shi = (const uint4*)g_Whi;
        const uint4* slo = (const uint4*)g_Wlo;
        for (int i = tid; i < 2048; i += 640) { dh[i] = shi[i]; dl[i] = slo[i]; }
        if (tid < HID) ((float2*)(sm + OFF_SWB))[tid] = g_w3b2[tid];
    }
    float bias3 = b3[0];
    u32 wHiB = base + OFF_WHI, wLoB = base + OFF_WLO;

    // consumer constants: warp tile = m 32 (wm 0..3) x n 32 (wn 0..3)
    int wm = (wid >> 2) & 3, wn = wid & 3;
    int li = lane & 7, grp = lane >> 3;
    int kgA = (grp >> 1) * 8;
    int kgB = (grp & 1) * 8;
    int nB0 = 32 * wn + (grp >> 1) * 8 + li;
    int nB1 = nB0 + 16;
    int bq0 = ((nB0 >> 3) << 10) + ((nB0 & 7) << 7);
    int bq1 = ((nB1 >> 3) << 10) + ((nB1 & 7) << 7);
    // A row-part per mt (2 x m16 tiles)
    int rp[2];
#pragma unroll
    for (int mt = 0; mt < 2; mt++) {
        int rA = wm * 32 + mt * 16 + (grp & 1) * 8 + li;
        rp[mt] = ((rA >> 3) << 10) + ((rA & 7) << 7);
    }

    // producer constants
    int tid_p = tid - 512;
    int lg = tid_p & 7, gr = tid_p >> 3;
    float4 dq[4];
    if (wid >= 16) {
#pragma unroll
        for (int i = 0; i < 4; i++) dq[i] = ((const float4*)g_d)[i * 8 + lg];
    }

    __syncthreads();  // W, swb staged

    // prologue: producers fill buf0 with this block's first tile
    int first = blockIdx.x;
    if (wid >= 16 && first < ntiles)
        k2_produce(first, E, is64, p64, p32, dq,
                   sm + OFF_H(0, 0), sm + OFF_H(0, 1), lg, gr);

    int iter = 0;
    for (int tile = first; tile < ntiles; tile += gridDim.x, iter++) {
        int buf = iter & 1;
        __syncthreads();  // H[buf] ready; H[buf^1] free

        if (wid < 16) {
            // ============ CONSUMERS: fused 3-pass MMA, m32 x n32 per warp ============
            u32 hHiB = base + OFF_H(buf, 0);
            u32 hLoB = base + OFF_H(buf, 1);

            float acc[2][4][4];
#pragma unroll
            for (int mt = 0; mt < 2; mt++)
#pragma unroll
                for (int nt = 0; nt < 4; nt++)
#pragma unroll
                    for (int q = 0; q < 4; q++) acc[mt][nt][q] = 0.f;

#pragma unroll 1
            for (int ks = 0; ks < 8; ks++) {
                int k0 = ks * 16;
                int kkA = k0 + kgA;
                int kpA = ((kkA >> 6) << 14) + ((kkA & 63) << 1);
                int kkB = k0 + kgB;
                int kpB = ((kkB >> 6) << 14) + ((kkB & 63) << 1);
                int oB0 = bq0 + kpB; oB0 ^= ((oB0 >> 3) & 0x70);
                int oB1 = bq1 + kpB; oB1 ^= ((oB1 >> 3) & 0x70);

                u32 bh0[4], bh1[4], bl0[4], bl1[4];
                ldsm4(bh0, wHiB + (u32)oB0);
                ldsm4(bh1, wHiB + (u32)oB1);
                ldsm4(bl0, wLoB + (u32)oB0);
                ldsm4(bl1, wLoB + (u32)oB1);

#pragma unroll
                for (int mt = 0; mt < 2; mt++) {
                    int oA = rp[mt] + kpA; oA ^= ((oA >> 3) & 0x70);
                    u32 aH[4], aL[4];
                    ldsm4(aH, hHiB + (u32)oA);
                    ldsm4(aL, hLoB + (u32)oA);
                    // hi x hi
                    mma16816(acc[mt][0], aH, bh0[0], bh0[1]);
                    mma16816(acc[mt][1], aH, bh0[2], bh0[3]);
                    mma16816(acc[mt][2], aH, bh1[0], bh1[1]);
                    mma16816(acc[mt][3], aH, bh1[2], bh1[3]);
                    // hi x lo
                    mma16816(acc[mt][0], aH, bl0[0], bl0[1]);
                    mma16816(acc[mt][1], aH, bl0[2], bl0[3]);
                    mma16816(acc[mt][2], aH, bl1[0], bl1[1]);
                    mma16816(acc[mt][3], aH, bl1[2], bl1[3]);
                    // lo x hi
                    mma16816(acc[mt][0], aL, bh0[0], bh0[1]);
                    mma16816(acc[mt][1], aL, bh0[2], bh0[3]);
                    mma16816(acc[mt][2], aL, bh1[0], bh1[1]);
                    mma16816(acc[mt][3], aL, bh1[2], bh1[3]);
                }
            }

            // epilogue: relu(acc + b2') . w3, quad-reduce, stash per-warp partial
#pragma unroll
            for (int mt = 0; mt < 2; mt++) {
                float pl = 0.f, ph = 0.f;
#pragma unroll
                for (int nt = 0; nt < 4; nt++)
#pragma unroll
                    for (int cp = 0; cp < 2; cp++) {
                        float2 w = swb[32 * wn + nt * 8 + 2 * (lane & 3) + cp];
                        pl = fmaf(fmaxf(acc[mt][nt][cp]     + w.x, 0.f), w.y, pl);
                        ph = fmaf(fmaxf(acc[mt][nt][2 + cp] + w.x, 0.f), w.y, ph);
                    }
                pl += __shfl_xor_sync(0xffffffffu, pl, 1);
                pl += __shfl_xor_sync(0xffffffffu, pl, 2);
                ph += __shfl_xor_sync(0xffffffffu, ph, 1);
                ph += __shfl_xor_sync(0xffffffffu, ph, 2);
                if ((lane & 3) == 0) {
                    int r = wm * 32 + mt * 16 + (lane >> 2);
                    sred[wn * 128 + r]     = pl;
                    sred[wn * 128 + r + 8] = ph;
                }
            }
            // consumer-only barrier, then final cross-warp sum + store
            asm volatile("bar.sync 1, 512;" ::: "memory");
            if (tid < TM) {
                long long ge = (long long)tile * TM + tid;
                if (ge < E) {
                    float v = sred[tid] + sred[128 + tid] + sred[256 + tid] + sred[384 + tid];
                    out[ge] = v + bias3;
                }
            }
        } else {
            // ============ PRODUCERS: transform tile+grid into H[buf^1] ============
            int nt = tile + gridDim.x;
            if (nt < ntiles)
                k2_produce(nt, E, is64, p64, p32, dq,
                           sm + OFF_H(buf ^ 1, 0), sm + OFF_H(buf ^ 1, 1), lg, gr);
        }
    }
}

// ---------------- launch ----------------
extern "C" void kernel_launch(void* const* d_in, const int* in_sizes, int n_in,
                              void* d_out, int out_size) {
    const float* z     = (const float*)d_in[0];
    const void*  ei    = d_in[1];
    const float* c     = (const float*)d_in[2];
    const float* W1    = (const float*)d_in[3];
    const float* b1    = (const float*)d_in[4];
    const float* gamma = (const float*)d_in[5];
    const float* beta  = (const float*)d_in[6];
    const float* W2    = (const float*)d_in[7];
    const float* b2    = (const float*)d_in[8];
    const float* W3    = (const float*)d_in[9];
    const float* b3    = (const float*)d_in[10];
    float* out = (float*)d_out;

    int N = in_sizes[0] / ZD;
    int E = in_sizes[1] / 2;

    cudaFuncSetAttribute(k2_main, cudaFuncAttributeMaxDynamicSharedMemorySize, K2_SMEM);

    k0_nodes<<<(N + NPB - 1) / NPB + 1, 128>>>(z, W1, N, (const unsigned int*)ei, c, b1);
    k1_stats<<<K1_BLOCKS, 128>>>(ei, E);
    k15_fold<<<1, 128>>>(gamma, beta, W2, b2, W3, 1.0 / (double)E);
    int ntiles = (E + TM - 1) / TM;
    k2_main<<<K2_GRID, 640, K2_SMEM>>>(ei, b3, out, E, ntiles);
}

// round 11
// speedup vs baseline: 3.4668x; 1.0920x over previous
#include <cuda_runtime.h>
#include <cuda_bf16.h>
#include <stdint.h>

#define NODES_MAX 50000
#define HID 128
#define ZD 64
#define NPB 16          // nodes per block in K0
#define TM 128          // edges per tile in K2
#define K1_BLOCKS 1184  // 148 SMs * 8
#define K2_GRID 148

typedef unsigned long long u64;
typedef unsigned int u32;

// ---------------- static device scratch ----------------
__device__ float  g_A[NODES_MAX * HID];     // z @ W1[0:64]
__device__ float  g_B[NODES_MAX * HID];     // z @ W1[64:128]
__device__ float  g_d[HID];                 // c @ W1[128:132] + b1
__device__ double g_sum[HID];
__device__ double g_sumsq[HID];
__device__ unsigned short g_Whi[16384];     // BN-folded W2 bf16-hi, MMA swizzled layout
__device__ unsigned short g_Wlo[16384];     // bf16-lo residual
__device__ float2 g_w3b2[HID];              // (b2_folded, w3) per feature
__device__ int    g_is64;

// ---------------- helpers ----------------
__device__ __forceinline__ u32 smem_u32(const void* p) {
    u32 a;
    asm("{ .reg .u64 t; cvta.to.shared.u64 t, %1; cvt.u32.u64 %0, t; }" : "=r"(a) : "l"(p));
    return a;
}
// packed bf16x2 convert: low half <- lo, high half <- hi
__device__ __forceinline__ u32 bf2(float lo, float hi) {
    u32 r;
    asm("cvt.rn.bf16x2.f32 %0, %1, %2;" : "=r"(r) : "f"(hi), "f"(lo));
    return r;
}
__device__ __forceinline__ void ldsm4(u32* r, u32 addr) {
    asm volatile("ldmatrix.sync.aligned.m8n8.x4.shared.b16 {%0,%1,%2,%3}, [%4];"
                 : "=r"(r[0]), "=r"(r[1]), "=r"(r[2]), "=r"(r[3]) : "r"(addr));
}
__device__ __forceinline__ void mma16816(float* c, const u32* a, u32 b0, u32 b1) {
    asm volatile(
        "mma.sync.aligned.m16n8k16.row.col.f32.bf16.bf16.f32 "
        "{%0,%1,%2,%3}, {%4,%5,%6,%7}, {%8,%9}, {%0,%1,%2,%3};"
        : "+f"(c[0]), "+f"(c[1]), "+f"(c[2]), "+f"(c[3])
        : "r"(a[0]), "r"(a[1]), "r"(a[2]), "r"(a[3]), "r"(b0), "r"(b1));
}

// MMA-layout byte offset for element (row r, col k) in a 128x128 bf16 K-major
// SW128 blocked-atom tile: atom = 8 rows x 64 bf16 (1024B), 16 atom-rows x 2 atom-cols.
__device__ __forceinline__ int bofs(int r, int k) {
    int off = ((r >> 3) << 10) + ((k >> 6) << 14) + ((r & 7) << 7) + ((k & 63) << 1);
    return off ^ ((off >> 3) & 0x70);
}

// ---------------- K0: per-node partial products (+fused detect & k0b in extra block) ----------------
__global__ void k0_nodes(const float* __restrict__ z, const float* __restrict__ W1, int N,
                         const unsigned int* __restrict__ eiw,
                         const float* __restrict__ c, const float* __restrict__ b1) {
    __shared__ float zs[NPB * ZD];
    int tid = threadIdx.x;

    if (blockIdx.x == gridDim.x - 1) {
        // --- fused k_detect: is edge_index int64 or int32? ---
        __shared__ int nz;
        if (tid == 0) nz = 0;
        __syncthreads();
        if (eiw[2 * tid + 1] != 0u) atomicAdd(&nz, 1);
        __syncthreads();
        if (tid == 0) g_is64 = (nz == 0) ? 1 : 0;
        // --- fused k0b: d = c@W1c + b1, zero BN accumulators ---
        float v = b1[tid];
#pragma unroll
        for (int k = 0; k < 4; k++) v = fmaf(c[k], W1[(2 * ZD + k) * HID + tid], v);
        g_d[tid]     = v;
        g_sum[tid]   = 0.0;
        g_sumsq[tid] = 0.0;
        return;
    }

    int base = blockIdx.x * NPB;
    int nn   = N - base; if (nn > NPB) nn = NPB;

    for (int i = tid; i < nn * ZD; i += 128) zs[i] = z[base * ZD + i];
    __syncthreads();

    float a[NPB], b[NPB];
#pragma unroll
    for (int n = 0; n < NPB; n++) { a[n] = 0.f; b[n] = 0.f; }

#pragma unroll 8
    for (int k = 0; k < ZD; k++) {
        float ws = W1[k * HID + tid];
        float wd = W1[(ZD + k) * HID + tid];
#pragma unroll
        for (int n = 0; n < NPB; n++) {
            float zk = zs[n * ZD + k];
            a[n] = fmaf(zk, ws, a[n]);
            b[n] = fmaf(zk, wd, b[n]);
        }
    }
    for (int n = 0; n < nn; n++) {
        g_A[(base + n) * HID + tid] = a[n];
        g_B[(base + n) * HID + tid] = b[n];
    }
}

// ---------------- K1: BN statistics pass ----------------
template<bool IS64>
__device__ __forceinline__ int ldi(const void* ei, long long pos) {
    return IS64 ? (int)((const long long*)ei)[pos] : ((const int*)ei)[pos];
}

template<bool IS64>
__device__ __forceinline__ void k1_body(const void* __restrict__ ei, int E) {
    int j = threadIdx.x;
    float dreg = g_d[j];

    int per = (E + gridDim.x - 1) / (int)gridDim.x;
    int e0 = blockIdx.x * per;
    int e1 = e0 + per; if (e1 > E) e1 = E;

    float s1 = 0.f, s2 = 0.f;
    int e = e0;
    for (; e + 8 <= e1; e += 8) {
        int s[8], t[8];
#pragma unroll
        for (int i = 0; i < 8; i++) s[i] = ldi<IS64>(ei, e + i);
#pragma unroll
        for (int i = 0; i < 8; i++) t[i] = ldi<IS64>(ei, (long long)E + e + i);
        float av[8], bv[8];
#pragma unroll
        for (int i = 0; i < 8; i++) { av[i] = g_A[s[i] * HID + j]; bv[i] = g_B[t[i] * HID + j]; }
#pragma unroll
        for (int i = 0; i < 8; i++) {
            float h = fmaxf(av[i] + bv[i] + dreg, 0.f);
            s1 += h; s2 = fmaf(h, h, s2);
        }
    }
    for (; e < e1; e++) {
        int s = ldi<IS64>(ei, e);
        int t = ldi<IS64>(ei, (long long)E + e);
        float h = fmaxf(g_A[s * HID + j] + g_B[t * HID + j] + dreg, 0.f);
        s1 += h; s2 = fmaf(h, h, s2);
    }
    atomicAdd(&g_sum[j],   (double)s1);
    atomicAdd(&g_sumsq[j], (double)s2);
}

__global__ void k1_stats(const void* __restrict__ ei, int E) {
    if (g_is64) k1_body<true>(ei, E);
    else        k1_body<false>(ei, E);
}

// ---------------- K1.5: fold BN into W2 (PARALLEL: 128 blocks, one per output feature) ----------------
// Block i handles output feature i; thread k handles input feature k.
__global__ void k15_fold(const float* __restrict__ gamma, const float* __restrict__ beta,
                         const float* __restrict__ W2, const float* __restrict__ b2,
                         const float* __restrict__ W3, double invE) {
    __shared__ float red[4];
    int i = blockIdx.x;    // output feature f
    int k = threadIdx.x;   // input feature k
    int lane = k & 31, wrp = k >> 5;

    // BN scale/shift for input feature k (recomputed per block; 2 LDGs, cheap)
    double m = g_sum[k] * invE;
    double v = g_sumsq[k] * invE - m * m;
    float x = (float)v + 1e-5f;
    float s = rsqrtf(x);
    s = s * (1.5f - 0.5f * x * s * s);  // Newton refine
    float g = s * gamma[k];
    float gsc_k = g;
    float gsh_k = beta[k] - (float)m * g;

    float w = W2[k * HID + i];           // W2[k][f=i]
    float wf = gsc_k * w;                // BN scale folded
    __nv_bfloat16 hb = __float2bfloat16(wf);
    float hf = __bfloat162float(hb);
    __nv_bfloat16 lb = __float2bfloat16(wf - hf);
    int o = bofs(i, k) >> 1;             // row = feature f, col = k
    g_Whi[o] = *(const unsigned short*)&hb;
    g_Wlo[o] = *(const unsigned short*)&lb;

    // reduce bb = sum_k gsh[k] * W2[k][i]
    float bb = gsh_k * w;
#pragma unroll
    for (int d = 16; d > 0; d >>= 1) bb += __shfl_xor_sync(0xffffffffu, bb, d);
    if (lane == 0) red[wrp] = bb;
    __syncthreads();
    if (k == 0) {
        float tot = red[0] + red[1] + red[2] + red[3];
        g_w3b2[i] = make_float2(b2[i] + tot, W3[i]);
    }
}

// ---------------- K2: warp-specialized producer/consumer ----------------
// 384 threads: warps 0-7 = MMA consumers (each m=64 x n=32, minimal smem replication),
// warps 8-11 = software-pipelined gather producers.
// smem (1024-aligned base):
#define OFF_WHI 0
#define OFF_WLO 32768
#define OFF_H(buf, part) (65536 + (buf) * 65536 + (part) * 32768)
#define OFF_SWB 196608          // w3b2 float2[128] (1KB)
#define OFF_SRED 197632         // sred[4][128] floats
#define K2_SMEM (199680 + 1024)

// producer: coalesced gather + relu + bf16 hi/lo split, SOFTWARE-PIPELINED.
// tid_p in [0,128): lg = tid_p&7 (16B chunk within 128B segment), gr = tid_p>>3 (row group).
static __device__ __forceinline__ void k2_produce(
    int tile, long long E, int is64, const long long* p64, const int* p32,
    const float4* dq, char* aHi, char* aLo, int lg, int gr)
{
    int sa[8], ta[8];
#pragma unroll
    for (int p = 0; p < 8; p++) {
        long long ge = (long long)tile * TM + p * 16 + gr;
        long long g2 = (ge < E) ? ge : (long long)0;
        sa[p] = is64 ? (int)p64[g2] : p32[g2];
        ta[p] = is64 ? (int)p64[E + g2] : p32[E + g2];
    }

    float4 av[2][4], bv[2][4];
    {
        const float4* ap = (const float4*)(g_A + (size_t)sa[0] * HID) + lg;
        const float4* bp = (const float4*)(g_B + (size_t)ta[0] * HID) + lg;
#pragma unroll
        for (int i = 0; i < 4; i++) av[0][i] = ap[i * 8];
#pragma unroll
        for (int i = 0; i < 4; i++) bv[0][i] = bp[i * 8];
    }

#pragma unroll
    for (int p = 0; p < 8; p++) {
        int cur = p & 1;
        if (p < 7) {
            const float4* ap = (const float4*)(g_A + (size_t)sa[p + 1] * HID) + lg;
            const float4* bp = (const float4*)(g_B + (size_t)ta[p + 1] * HID) + lg;
#pragma unroll
            for (int i = 0; i < 4; i++) av[cur ^ 1][i] = ap[i * 8];
#pragma unroll
            for (int i = 0; i < 4; i++) bv[cur ^ 1][i] = bp[i * 8];
        }
        int r = p * 16 + gr;
#pragma unroll
        for (int i = 0; i < 4; i++) {
            float4 d = dq[i];
            float4 a = av[cur][i], b = bv[cur][i];
            float h0 = fmaxf(a.x + b.x + d.x, 0.f);
            float h1 = fmaxf(a.y + b.y + d.y, 0.f);
            float h2 = fmaxf(a.z + b.z + d.z, 0.f);
            float h3 = fmaxf(a.w + b.w + d.w, 0.f);
            u32 ph0 = bf2(h0, h1), ph1 = bf2(h2, h3);
            float r00 = __uint_as_float(ph0 << 16);
            float r01 = __uint_as_float(ph0 & 0xFFFF0000u);
            float r10 = __uint_as_float(ph1 << 16);
            float r11 = __uint_as_float(ph1 & 0xFFFF0000u);
            u32 pl0 = bf2(h0 - r00, h1 - r01);
            u32 pl1 = bf2(h2 - r10, h3 - r11);
            int o = bofs(r, i * 32 + lg * 4);
            *(uint2*)(aHi + o) = make_uint2(ph0, ph1);
            *(uint2*)(aLo + o) = make_uint2(pl0, pl1);
        }
    }
}

__global__ void __launch_bounds__(384, 1)
k2_main(const void* __restrict__ ei, const float* __restrict__ b3,
        float* __restrict__ out, int E, int ntiles) {
    extern __shared__ char dsm[];
    u32 braw = smem_u32(dsm);
    u32 base = (braw + 1023u) & ~1023u;
    char* sm = dsm + (base - braw);

    int tid  = threadIdx.x;
    int wid  = tid >> 5, lane = tid & 31;
    int is64 = g_is64;
    const long long* p64 = (const long long*)ei;
    const int*       p32 = (const int*)ei;

    const float2* swb = (const float2*)(sm + OFF_SWB);
    float* sred = (float*)(sm + OFF_SRED);

    // stage W2' bf16 hi/lo + w3b2 into smem (all 384 threads)
    {
        uint4* dh = (uint4*)(sm + OFF_WHI);
        uint4* dl = (uint4*)(sm + OFF_WLO);
        const uint4* shi = (const uint4*)g_Whi;
        const uint4* slo = (const uint4*)g_Wlo;
        for (int i = tid; i < 2048; i += 384) { dh[i] = shi[i]; dl[i] = slo[i]; }
        if (tid < HID) ((float2*)(sm + OFF_SWB))[tid] = g_w3b2[tid];
    }
    float bias3 = b3[0];
    u32 wHiB = base + OFF_WHI, wLoB = base + OFF_WLO;

    // consumer constants: warp tile = m 64 (wm 0..1) x n 32 (wn 0..3)
    int wm = (wid >> 2) & 1, wn = wid & 3;
    int li = lane & 7, grp = lane >> 3;
    int kgA = (grp >> 1) * 8;
    int kgB = (grp & 1) * 8;
    int nB0 = 32 * wn + (grp >> 1) * 8 + li;
    int nB1 = nB0 + 16;
    int bq0 = ((nB0 >> 3) << 10) + ((nB0 & 7) << 7);
    int bq1 = ((nB1 >> 3) << 10) + ((nB1 & 7) << 7);
    // A row-part per mt (4 x m16 tiles)
    int rp[4];
#pragma unroll
    for (int mt = 0; mt < 4; mt++) {
        int rA = wm * 64 + mt * 16 + (grp & 1) * 8 + li;
        rp[mt] = ((rA >> 3) << 10) + ((rA & 7) << 7);
    }

    // producer constants
    int tid_p = tid - 256;
    int lg = tid_p & 7, gr = tid_p >> 3;
    float4 dq[4];
    if (wid >= 8) {
#pragma unroll
        for (int i = 0; i < 4; i++) dq[i] = ((const float4*)g_d)[i * 8 + lg];
    }

    __syncthreads();  // W, swb staged

    // prologue: producers fill buf0 with this block's first tile
    int first = blockIdx.x;
    if (wid >= 8 && first < ntiles)
        k2_produce(first, E, is64, p64, p32, dq,
                   sm + OFF_H(0, 0), sm + OFF_H(0, 1), lg, gr);

    int iter = 0;
    for (int tile = first; tile < ntiles; tile += gridDim.x, iter++) {
        int buf = iter & 1;
        __syncthreads();  // H[buf] ready; H[buf^1] free

        if (wid < 8) {
            // ============ CONSUMERS: fused 3-pass MMA, m64 x n32 per warp ============
            u32 hHiB = base + OFF_H(buf, 0);
            u32 hLoB = base + OFF_H(buf, 1);

            float acc[4][4][4];
#pragma unroll
            for (int mt = 0; mt < 4; mt++)
#pragma unroll
                for (int nt = 0; nt < 4; nt++)
#pragma unroll
                    for (int q = 0; q < 4; q++) acc[mt][nt][q] = 0.f;

#pragma unroll 1
            for (int ks = 0; ks < 8; ks++) {
                int k0 = ks * 16;
                int kkA = k0 + kgA;
                int kpA = ((kkA >> 6) << 14) + ((kkA & 63) << 1);
                int kkB = k0 + kgB;
                int kpB = ((kkB >> 6) << 14) + ((kkB & 63) << 1);
                int oB0 = bq0 + kpB; oB0 ^= ((oB0 >> 3) & 0x70);
                int oB1 = bq1 + kpB; oB1 ^= ((oB1 >> 3) & 0x70);

                u32 bh0[4], bh1[4], bl0[4], bl1[4];
                ldsm4(bh0, wHiB + (u32)oB0);
                ldsm4(bh1, wHiB + (u32)oB1);
                ldsm4(bl0, wLoB + (u32)oB0);
                ldsm4(bl1, wLoB + (u32)oB1);

                u32 aH[4][4], aL[4][4];
#pragma unroll
                for (int mt = 0; mt < 4; mt++) {
                    int oA = rp[mt] + kpA; oA ^= ((oA >> 3) & 0x70);
                    ldsm4(aH[mt], hHiB + (u32)oA);
                    ldsm4(aL[mt], hLoB + (u32)oA);
                }

#pragma unroll
                for (int mt = 0; mt < 4; mt++) {
                    // hi x hi
                    mma16816(acc[mt][0], aH[mt], bh0[0], bh0[1]);
                    mma16816(acc[mt][1], aH[mt], bh0[2], bh0[3]);
                    mma16816(acc[mt][2], aH[mt], bh1[0], bh1[1]);
                    mma16816(acc[mt][3], aH[mt], bh1[2], bh1[3]);
                    // hi x lo
                    mma16816(acc[mt][0], aH[mt], bl0[0], bl0[1]);
                    mma16816(acc[mt][1], aH[mt], bl0[2], bl0[3]);
                    mma16816(acc[mt][2], aH[mt], bl1[0], bl1[1]);
                    mma16816(acc[mt][3], aH[mt], bl1[2], bl1[3]);
                    // lo x hi
                    mma16816(acc[mt][0], aL[mt], bh0[0], bh0[1]);
                    mma16816(acc[mt][1], aL[mt], bh0[2], bh0[3]);
                    mma16816(acc[mt][2], aL[mt], bh1[0], bh1[1]);
                    mma16816(acc[mt][3], aL[mt], bh1[2], bh1[3]);
                }
            }

            // epilogue: relu(acc + b2') . w3, quad-reduce, stash per-warp partial
#pragma unroll
            for (int mt = 0; mt < 4; mt++) {
                float pl = 0.f, ph = 0.f;
#pragma unroll
                for (int nt = 0; nt < 4; nt++)
#pragma unroll
                    for (int cp = 0; cp < 2; cp++) {
                        float2 w = swb[32 * wn + nt * 8 + 2 * (lane & 3) + cp];
                        pl = fmaf(fmaxf(acc[mt][nt][cp]     + w.x, 0.f), w.y, pl);
                        ph = fmaf(fmaxf(acc[mt][nt][2 + cp] + w.x, 0.f), w.y, ph);
                    }
                pl += __shfl_xor_sync(0xffffffffu, pl, 1);
                pl += __shfl_xor_sync(0xffffffffu, pl, 2);
                ph += __shfl_xor_sync(0xffffffffu, ph, 1);
                ph += __shfl_xor_sync(0xffffffffu, ph, 2);
                if ((lane & 3) == 0) {
                    int r = wm * 64 + mt * 16 + (lane >> 2);
                    sred[wn * 128 + r]     = pl;
                    sred[wn * 128 + r + 8] = ph;
                }
            }
            // consumer-only barrier, then final cross-warp sum + store
            asm volatile("bar.sync 1, 256;" ::: "memory");
            if (tid < TM) {
                long long ge = (long long)tile * TM + tid;
                if (ge < E) {
                    float v = sred[tid] + sred[128 + tid] + sred[256 + tid] + sred[384 + tid];
                    out[ge] = v + bias3;
                }
            }
        } else {
            // ============ PRODUCERS: transform tile+grid into H[buf^1] ============
            int nt = tile + gridDim.x;
            if (nt < ntiles)
                k2_produce(nt, E, is64, p64, p32, dq,
                           sm + OFF_H(buf ^ 1, 0), sm + OFF_H(buf ^ 1, 1), lg, gr);
        }
    }
}

// ---------------- launch ----------------
extern "C" void kernel_launch(void* const* d_in, const int* in_sizes, int n_in,
                              void* d_out, int out_size) {
    const float* z     = (const float*)d_in[0];
    const void*  ei    = d_in[1];
    const float* c     = (const float*)d_in[2];
    const float* W1    = (const float*)d_in[3];
    const float* b1    = (const float*)d_in[4];
    const float* gamma = (const float*)d_in[5];
    const float* beta  = (const float*)d_in[6];
    const float* W2    = (const float*)d_in[7];
    const float* b2    = (const float*)d_in[8];
    const float* W3    = (const float*)d_in[9];
    const float* b3    = (const float*)d_in[10];
    float* out = (float*)d_out;

    int N = in_sizes[0] / ZD;
    int E = in_sizes[1] / 2;

    cudaFuncSetAttribute(k2_main, cudaFuncAttributeMaxDynamicSharedMemorySize, K2_SMEM);

    k0_nodes<<<(N + NPB - 1) / NPB + 1, 128>>>(z, W1, N, (const unsigned int*)ei, c, b1);
    k1_stats<<<K1_BLOCKS, 128>>>(ei, E);
    k15_fold<<<HID, 128>>>(gamma, beta, W2, b2, W3, 1.0 / (double)E);
    int ntiles = (E + TM - 1) / TM;
    k2_main<<<K2_GRID, 384, K2_SMEM>>>(ei, b3, out, E, ntiles);
}

// round 12
// speedup vs baseline: 3.4810x; 1.0041x over previous
#include <cuda_runtime.h>
#include <cuda_bf16.h>
#include <stdint.h>

#define NODES_MAX 50000
#define HID 128
#define ZD 64
#define NPB 16          // nodes per block in K0
#define TM 128          // edges per tile in K2
#define K1_BLOCKS 1184  // 148 SMs * 8
#define K2_GRID 148

typedef unsigned long long u64;
typedef unsigned int u32;

// ---------------- static device scratch ----------------
__device__ float  g_A[NODES_MAX * HID];     // z @ W1[0:64]
__device__ float  g_B[NODES_MAX * HID];     // z @ W1[64:128]
__device__ float  g_d[HID];                 // c @ W1[128:132] + b1
__device__ double g_sum[HID];
__device__ double g_sumsq[HID];
__device__ unsigned short g_Whi[16384];     // BN-folded W2 bf16-hi, MMA swizzled layout
__device__ unsigned short g_Wlo[16384];     // bf16-lo residual
__device__ float2 g_w3b2[HID];              // (b2_folded, w3) per feature
__device__ int    g_is64;

// ---------------- helpers ----------------
__device__ __forceinline__ u32 smem_u32(const void* p) {
    u32 a;
    asm("{ .reg .u64 t; cvta.to.shared.u64 t, %1; cvt.u32.u64 %0, t; }" : "=r"(a) : "l"(p));
    return a;
}
// packed bf16x2 convert: low half <- lo, high half <- hi
__device__ __forceinline__ u32 bf2(float lo, float hi) {
    u32 r;
    asm("cvt.rn.bf16x2.f32 %0, %1, %2;" : "=r"(r) : "f"(hi), "f"(lo));
    return r;
}
__device__ __forceinline__ void ldsm4(u32* r, u32 addr) {
    asm volatile("ldmatrix.sync.aligned.m8n8.x4.shared.b16 {%0,%1,%2,%3}, [%4];"
                 : "=r"(r[0]), "=r"(r[1]), "=r"(r[2]), "=r"(r[3]) : "r"(addr));
}
__device__ __forceinline__ void mma16816(float* c, const u32* a, u32 b0, u32 b1) {
    asm volatile(
        "mma.sync.aligned.m16n8k16.row.col.f32.bf16.bf16.f32 "
        "{%0,%1,%2,%3}, {%4,%5,%6,%7}, {%8,%9}, {%0,%1,%2,%3};"
        : "+f"(c[0]), "+f"(c[1]), "+f"(c[2]), "+f"(c[3])
        : "r"(a[0]), "r"(a[1]), "r"(a[2]), "r"(a[3]), "r"(b0), "r"(b1));
}

// MMA-layout byte offset for element (row r, col k) in a 128x128 bf16 K-major
// SW128 blocked-atom tile: atom = 8 rows x 64 bf16 (1024B), 16 atom-rows x 2 atom-cols.
__device__ __forceinline__ int bofs(int r, int k) {
    int off = ((r >> 3) << 10) + ((k >> 6) << 14) + ((r & 7) << 7) + ((k & 63) << 1);
    return off ^ ((off >> 3) & 0x70);
}

// ---------------- K0: per-node partial products (+fused detect & k0b in extra block) ----------------
__global__ void k0_nodes(const float* __restrict__ z, const float* __restrict__ W1, int N,
                         const unsigned int* __restrict__ eiw,
                         const float* __restrict__ c, const float* __restrict__ b1) {
    __shared__ float zs[NPB * ZD];
    int tid = threadIdx.x;

    if (blockIdx.x == gridDim.x - 1) {
        // --- fused k_detect: is edge_index int64 or int32? ---
        __shared__ int nz;
        if (tid == 0) nz = 0;
        __syncthreads();
        if (eiw[2 * tid + 1] != 0u) atomicAdd(&nz, 1);
        __syncthreads();
        if (tid == 0) g_is64 = (nz == 0) ? 1 : 0;
        // --- fused k0b: d = c@W1c + b1, zero BN accumulators ---
        float v = b1[tid];
#pragma unroll
        for (int k = 0; k < 4; k++) v = fmaf(c[k], W1[(2 * ZD + k) * HID + tid], v);
        g_d[tid]     = v;
        g_sum[tid]   = 0.0;
        g_sumsq[tid] = 0.0;
        return;
    }

    int base = blockIdx.x * NPB;
    int nn   = N - base; if (nn > NPB) nn = NPB;

    for (int i = tid; i < nn * ZD; i += 128) zs[i] = z[base * ZD + i];
    __syncthreads();

    float a[NPB], b[NPB];
#pragma unroll
    for (int n = 0; n < NPB; n++) { a[n] = 0.f; b[n] = 0.f; }

#pragma unroll 8
    for (int k = 0; k < ZD; k++) {
        float ws = W1[k * HID + tid];
        float wd = W1[(ZD + k) * HID + tid];
#pragma unroll
        for (int n = 0; n < NPB; n++) {
            float zk = zs[n * ZD + k];
            a[n] = fmaf(zk, ws, a[n]);
            b[n] = fmaf(zk, wd, b[n]);
        }
    }
    for (int n = 0; n < nn; n++) {
        g_A[(base + n) * HID + tid] = a[n];
        g_B[(base + n) * HID + tid] = b[n];
    }
}

// ---------------- K1: BN statistics pass ----------------
template<bool IS64>
__device__ __forceinline__ int ldi(const void* ei, long long pos) {
    return IS64 ? (int)((const long long*)ei)[pos] : ((const int*)ei)[pos];
}

template<bool IS64>
__device__ __forceinline__ void k1_body(const void* __restrict__ ei, int E) {
    int j = threadIdx.x;
    float dreg = g_d[j];

    int per = (E + gridDim.x - 1) / (int)gridDim.x;
    int e0 = blockIdx.x * per;
    int e1 = e0 + per; if (e1 > E) e1 = E;

    float s1 = 0.f, s2 = 0.f;
    int e = e0;
    for (; e + 16 <= e1; e += 16) {
        int s[16], t[16];
#pragma unroll
        for (int i = 0; i < 16; i++) s[i] = ldi<IS64>(ei, e + i);
#pragma unroll
        for (int i = 0; i < 16; i++) t[i] = ldi<IS64>(ei, (long long)E + e + i);
        float av[16], bv[16];
#pragma unroll
        for (int i = 0; i < 16; i++) { av[i] = g_A[s[i] * HID + j]; bv[i] = g_B[t[i] * HID + j]; }
#pragma unroll
        for (int i = 0; i < 16; i++) {
            float h = fmaxf(av[i] + bv[i] + dreg, 0.f);
            s1 += h; s2 = fmaf(h, h, s2);
        }
    }
    for (; e < e1; e++) {
        int s = ldi<IS64>(ei, e);
        int t = ldi<IS64>(ei, (long long)E + e);
        float h = fmaxf(g_A[s * HID + j] + g_B[t * HID + j] + dreg, 0.f);
        s1 += h; s2 = fmaf(h, h, s2);
    }
    atomicAdd(&g_sum[j],   (double)s1);
    atomicAdd(&g_sumsq[j], (double)s2);
}

__global__ void __launch_bounds__(128, 8) k1_stats(const void* __restrict__ ei, int E) {
    if (g_is64) k1_body<true>(ei, E);
    else        k1_body<false>(ei, E);
}

// ---------------- K1.5: fold BN into W2 (PARALLEL: 128 blocks, one per output feature) ----------------
__global__ void k15_fold(const float* __restrict__ gamma, const float* __restrict__ beta,
                         const float* __restrict__ W2, const float* __restrict__ b2,
                         const float* __restrict__ W3, double invE) {
    __shared__ float red[4];
    int i = blockIdx.x;    // output feature f
    int k = threadIdx.x;   // input feature k
    int lane = k & 31, wrp = k >> 5;

    double m = g_sum[k] * invE;
    double v = g_sumsq[k] * invE - m * m;
    float x = (float)v + 1e-5f;
    float s = rsqrtf(x);
    s = s * (1.5f - 0.5f * x * s * s);  // Newton refine
    float g = s * gamma[k];
    float gsc_k = g;
    float gsh_k = beta[k] - (float)m * g;

    float w = W2[k * HID + i];           // W2[k][f=i]
    float wf = gsc_k * w;                // BN scale folded
    __nv_bfloat16 hb = __float2bfloat16(wf);
    float hf = __bfloat162float(hb);
    __nv_bfloat16 lb = __float2bfloat16(wf - hf);
    int o = bofs(i, k) >> 1;             // row = feature f, col = k
    g_Whi[o] = *(const unsigned short*)&hb;
    g_Wlo[o] = *(const unsigned short*)&lb;

    float bb = gsh_k * w;
#pragma unroll
    for (int d = 16; d > 0; d >>= 1) bb += __shfl_xor_sync(0xffffffffu, bb, d);
    if (lane == 0) red[wrp] = bb;
    __syncthreads();
    if (k == 0) {
        float tot = red[0] + red[1] + red[2] + red[3];
        g_w3b2[i] = make_float2(b2[i] + tot, W3[i]);
    }
}

// ---------------- K2: warp-specialized producer/consumer ----------------
// 384 threads: warps 0-7 = MMA consumers (each m=64 x n=32),
// warps 8-11 = pipelined gather producers + OUTPUT EPILOGUE (offloaded from consumers).
// smem (1024-aligned base):
#define OFF_WHI 0
#define OFF_WLO 32768
#define OFF_H(buf, part) (65536 + (buf) * 65536 + (part) * 32768)
#define OFF_SWB 196608          // w3b2 float2[128] (1KB)
#define OFF_SRED 197632         // sred[4][128] floats
#define K2_SMEM (199680 + 1024)

// producer: coalesced gather + relu + bf16 hi/lo split, SOFTWARE-PIPELINED.
static __device__ __forceinline__ void k2_produce(
    int tile, long long E, int is64, const long long* p64, const int* p32,
    const float4* dq, char* aHi, char* aLo, int lg, int gr)
{
    int sa[8], ta[8];
#pragma unroll
    for (int p = 0; p < 8; p++) {
        long long ge = (long long)tile * TM + p * 16 + gr;
        long long g2 = (ge < E) ? ge : (long long)0;
        sa[p] = is64 ? (int)p64[g2] : p32[g2];
        ta[p] = is64 ? (int)p64[E + g2] : p32[E + g2];
    }

    float4 av[2][4], bv[2][4];
    {
        const float4* ap = (const float4*)(g_A + (size_t)sa[0] * HID) + lg;
        const float4* bp = (const float4*)(g_B + (size_t)ta[0] * HID) + lg;
#pragma unroll
        for (int i = 0; i < 4; i++) av[0][i] = ap[i * 8];
#pragma unroll
        for (int i = 0; i < 4; i++) bv[0][i] = bp[i * 8];
    }

#pragma unroll
    for (int p = 0; p < 8; p++) {
        int cur = p & 1;
        if (p < 7) {
            const float4* ap = (const float4*)(g_A + (size_t)sa[p + 1] * HID) + lg;
            const float4* bp = (const float4*)(g_B + (size_t)ta[p + 1] * HID) + lg;
#pragma unroll
            for (int i = 0; i < 4; i++) av[cur ^ 1][i] = ap[i * 8];
#pragma unroll
            for (int i = 0; i < 4; i++) bv[cur ^ 1][i] = bp[i * 8];
        }
        int r = p * 16 + gr;
#pragma unroll
        for (int i = 0; i < 4; i++) {
            float4 d = dq[i];
            float4 a = av[cur][i], b = bv[cur][i];
            float h0 = fmaxf(a.x + b.x + d.x, 0.f);
            float h1 = fmaxf(a.y + b.y + d.y, 0.f);
            float h2 = fmaxf(a.z + b.z + d.z, 0.f);
            float h3 = fmaxf(a.w + b.w + d.w, 0.f);
            u32 ph0 = bf2(h0, h1), ph1 = bf2(h2, h3);
            float r00 = __uint_as_float(ph0 << 16);
            float r01 = __uint_as_float(ph0 & 0xFFFF0000u);
            float r10 = __uint_as_float(ph1 << 16);
            float r11 = __uint_as_float(ph1 & 0xFFFF0000u);
            u32 pl0 = bf2(h0 - r00, h1 - r01);
            u32 pl1 = bf2(h2 - r10, h3 - r11);
            int o = bofs(r, i * 32 + lg * 4);
            *(uint2*)(aHi + o) = make_uint2(ph0, ph1);
            *(uint2*)(aLo + o) = make_uint2(pl0, pl1);
        }
    }
}

__global__ void __launch_bounds__(384, 1)
k2_main(const void* __restrict__ ei, const float* __restrict__ b3,
        float* __restrict__ out, int E, int ntiles) {
    extern __shared__ char dsm[];
    u32 braw = smem_u32(dsm);
    u32 base = (braw + 1023u) & ~1023u;
    char* sm = dsm + (base - braw);

    int tid  = threadIdx.x;
    int wid  = tid >> 5, lane = tid & 31;
    int is64 = g_is64;
    const long long* p64 = (const long long*)ei;
    const int*       p32 = (const int*)ei;

    const float2* swb = (const float2*)(sm + OFF_SWB);
    float* sred = (float*)(sm + OFF_SRED);

    // stage W2' bf16 hi/lo + w3b2 into smem (all 384 threads)
    {
        uint4* dh = (uint4*)(sm + OFF_WHI);
        uint4* dl = (uint4*)(sm + OFF_WLO);
        const uint4* shi = (const uint4*)g_Whi;
        const uint4* slo = (const uint4*)g_Wlo;
        for (int i = tid; i < 2048; i += 384) { dh[i] = shi[i]; dl[i] = slo[i]; }
        if (tid < HID) ((float2*)(sm + OFF_SWB))[tid] = g_w3b2[tid];
    }
    float bias3 = b3[0];
    u32 wHiB = base + OFF_WHI, wLoB = base + OFF_WLO;

    // consumer constants: warp tile = m 64 (wm 0..1) x n 32 (wn 0..3)
    int wm = (wid >> 2) & 1, wn = wid & 3;
    int li = lane & 7, grp = lane >> 3;
    int kgA = (grp >> 1) * 8;
    int kgB = (grp & 1) * 8;
    int nB0 = 32 * wn + (grp >> 1) * 8 + li;
    int nB1 = nB0 + 16;
    int bq0 = ((nB0 >> 3) << 10) + ((nB0 & 7) << 7);
    int bq1 = ((nB1 >> 3) << 10) + ((nB1 & 7) << 7);
    // A row-part per mt (4 x m16 tiles)
    int rp[4];
#pragma unroll
    for (int mt = 0; mt < 4; mt++) {
        int rA = wm * 64 + mt * 16 + (grp & 1) * 8 + li;
        rp[mt] = ((rA >> 3) << 10) + ((rA & 7) << 7);
    }

    // producer constants
    int tid_p = tid - 256;
    int lg = tid_p & 7, gr = tid_p >> 3;
    float4 dq[4];
    if (wid >= 8) {
#pragma unroll
        for (int i = 0; i < 4; i++) dq[i] = ((const float4*)g_d)[i * 8 + lg];
    }

    __syncthreads();  // W, swb staged

    // prologue: producers fill buf0 with this block's first tile
    int first = blockIdx.x;
    if (wid >= 8 && first < ntiles)
        k2_produce(first, E, is64, p64, p32, dq,
                   sm + OFF_H(0, 0), sm + OFF_H(0, 1), lg, gr);

    int iter = 0;
    for (int tile = first; tile < ntiles; tile += gridDim.x, iter++) {
        int buf = iter & 1;
        __syncthreads();  // H[buf] ready; H[buf^1] free; sred(prev) consumed by producers

        if (wid < 8) {
            // ============ CONSUMERS: fused 3-pass MMA, m64 x n32 per warp ============
            u32 hHiB = base + OFF_H(buf, 0);
            u32 hLoB = base + OFF_H(buf, 1);

            float acc[4][4][4];
#pragma unroll
            for (int mt = 0; mt < 4; mt++)
#pragma unroll
                for (int nt = 0; nt < 4; nt++)
#pragma unroll
                    for (int q = 0; q < 4; q++) acc[mt][nt][q] = 0.f;

#pragma unroll 1
            for (int ks = 0; ks < 8; ks++) {
                int k0 = ks * 16;
                int kkA = k0 + kgA;
                int kpA = ((kkA >> 6) << 14) + ((kkA & 63) << 1);
                int kkB = k0 + kgB;
                int kpB = ((kkB >> 6) << 14) + ((kkB & 63) << 1);
                int oB0 = bq0 + kpB; oB0 ^= ((oB0 >> 3) & 0x70);
                int oB1 = bq1 + kpB; oB1 ^= ((oB1 >> 3) & 0x70);

                u32 bh0[4], bh1[4], bl0[4], bl1[4];
                ldsm4(bh0, wHiB + (u32)oB0);
                ldsm4(bh1, wHiB + (u32)oB1);
                ldsm4(bl0, wLoB + (u32)oB0);
                ldsm4(bl1, wLoB + (u32)oB1);

                u32 aH[4][4], aL[4][4];
#pragma unroll
                for (int mt = 0; mt < 4; mt++) {
                    int oA = rp[mt] + kpA; oA ^= ((oA >> 3) & 0x70);
                    ldsm4(aH[mt], hHiB + (u32)oA);
                    ldsm4(aL[mt], hLoB + (u32)oA);
                }

                // pass-major ordering: acc reuse distance = 16 MMAs
#pragma unroll
                for (int mt = 0; mt < 4; mt++) {           // hi x hi
                    mma16816(acc[mt][0], aH[mt], bh0[0], bh0[1]);
                    mma16816(acc[mt][1], aH[mt], bh0[2], bh0[3]);
                    mma16816(acc[mt][2], aH[mt], bh1[0], bh1[1]);
                    mma16816(acc[mt][3], aH[mt], bh1[2], bh1[3]);
                }
#pragma unroll
                for (int mt = 0; mt < 4; mt++) {           // hi x lo
                    mma16816(acc[mt][0], aH[mt], bl0[0], bl0[1]);
                    mma16816(acc[mt][1], aH[mt], bl0[2], bl0[3]);
                    mma16816(acc[mt][2], aH[mt], bl1[0], bl1[1]);
                    mma16816(acc[mt][3], aH[mt], bl1[2], bl1[3]);
                }
#pragma unroll
                for (int mt = 0; mt < 4; mt++) {           // lo x hi
                    mma16816(acc[mt][0], aL[mt], bh0[0], bh0[1]);
                    mma16816(acc[mt][1], aL[mt], bh0[2], bh0[3]);
                    mma16816(acc[mt][2], aL[mt], bh1[0], bh1[1]);
                    mma16816(acc[mt][3], aL[mt], bh1[2], bh1[3]);
                }
            }

            // epilogue (consumer part): relu(acc + b2') . w3, quad-reduce, stash partials
#pragma unroll
            for (int mt = 0; mt < 4; mt++) {
                float pl = 0.f, ph = 0.f;
#pragma unroll
                for (int nt = 0; nt < 4; nt++)
#pragma unroll
                    for (int cp = 0; cp < 2; cp++) {
                        float2 w = swb[32 * wn + nt * 8 + 2 * (lane & 3) + cp];
                        pl = fmaf(fmaxf(acc[mt][nt][cp]     + w.x, 0.f), w.y, pl);
                        ph = fmaf(fmaxf(acc[mt][nt][2 + cp] + w.x, 0.f), w.y, ph);
                    }
                pl += __shfl_xor_sync(0xffffffffu, pl, 1);
                pl += __shfl_xor_sync(0xffffffffu, pl, 2);
                ph += __shfl_xor_sync(0xffffffffu, ph, 1);
                ph += __shfl_xor_sync(0xffffffffu, ph, 2);
                if ((lane & 3) == 0) {
                    int r = wm * 64 + mt * 16 + (lane >> 2);
                    sred[wn * 128 + r]     = pl;
                    sred[wn * 128 + r + 8] = ph;
                }
            }
            // non-blocking arrive: producers pick up the final sum + store
            asm volatile("bar.arrive 1, 384;" ::: "memory");
        } else {
            // ============ PRODUCERS: transform tile+grid into H[buf^1], then output epilogue ============
            int nt = tile + gridDim.x;
            if (nt < ntiles)
                k2_produce(nt, E, is64, p64, p32, dq,
                           sm + OFF_H(buf ^ 1, 0), sm + OFF_H(buf ^ 1, 1), lg, gr);

            asm volatile("bar.sync 1, 384;" ::: "memory");  // wait for consumer sred
            long long ge = (long long)tile * TM + tid_p;
            if (ge < E) {
                float v = sred[tid_p] + sred[128 + tid_p] + sred[256 + tid_p] + sred[384 + tid_p];
                out[ge] = v + bias3;
            }
        }
    }
}

// ---------------- launch ----------------
extern "C" void kernel_launch(void* const* d_in, const int* in_sizes, int n_in,
                              void* d_out, int out_size) {
    const float* z     = (const float*)d_in[0];
    const void*  ei    = d_in[1];
    const float* c     = (const float*)d_in[2];
    const float* W1    = (const float*)d_in[3];
    const float* b1    = (const float*)d_in[4];
    const float* gamma = (const float*)d_in[5];
    const float* beta  = (const float*)d_in[6];
    const float* W2    = (const float*)d_in[7];
    const float* b2    = (const float*)d_in[8];
    const float* W3    = (const float*)d_in[9];
    const float* b3    = (const float*)d_in[10];
    float* out = (float*)d_out;

    int N = in_sizes[0] / ZD;
    int E = in_sizes[1] / 2;

    cudaFuncSetAttribute(k2_main, cudaFuncAttributeMaxDynamicSharedMemorySize, K2_SMEM);

    k0_nodes<<<(N + NPB - 1) / NPB + 1, 128>>>(z, W1, N, (const unsigned int*)ei, c, b1);
    k1_stats<<<K1_BLOCKS, 128>>>(ei, E);
    k15_fold<<<HID, 128>>>(gamma, beta, W2, b2, W3, 1.0 / (double)E);
    int ntiles = (E + TM - 1) / TM;
    k2_main<<<K2_GRID, 384, K2_SMEM>>>(ei, b3, out, E, ntiles);
}